// round 4
// baseline (speedup 1.0000x reference)
#include <cuda_runtime.h>
#include <math.h>

#define BATCH 65536
#define FULL 0xffffffffu

// -------- device scratch (allocation-free rule: __device__ globals) --------
__device__ float g_xd[(size_t)BATCH * 420];   // decomp-1 output, channel-major [d][t]
__device__ float g_f [(size_t)BATCH * 420];   // DyConv output
__device__ float g_hh[(size_t)BATCH * 256];   // relu(f@W1+b1)
__device__ float g_hr[(size_t)BATCH * 64];    // hh@W2 + f@Wres + b2 + bres

// ============================================================================
// Kernel A1: conv embed + autocorrelation attention + residual + decomp1
// 1 warp = 1 sample, lane t in [0,30) holds the 14-channel row in registers.
// ============================================================================
__global__ __launch_bounds__(256) void kA1(
    const float* __restrict__ x,
    const float* __restrict__ W_emb, const float* __restrict__ b_emb,
    const float* __restrict__ Wq, const float* __restrict__ bq,
    const float* __restrict__ Wk, const float* __restrict__ bk,
    const float* __restrict__ Wv, const float* __restrict__ bv,
    const float* __restrict__ Wo, const float* __restrict__ bo)
{
    __shared__ float sWe[588], sbe[14];
    __shared__ float sWq[112], sWk[112], sWv[112];
    __shared__ float sbq[8], sbk[8], sbv[8];
    __shared__ float sWo[112], sbo[14];
    __shared__ float scr[8][512];   // per-warp: x staging, then qs[8][32]|ks[8][32]

    const int tid = threadIdx.x;
    for (int i = tid; i < 588; i += 256) sWe[i] = W_emb[i];
    for (int i = tid; i < 112; i += 256) { sWq[i]=Wq[i]; sWk[i]=Wk[i]; sWv[i]=Wv[i]; sWo[i]=Wo[i]; }
    if (tid < 14) { sbe[tid]=b_emb[tid]; sbo[tid]=bo[tid]; }
    if (tid < 8)  { sbq[tid]=bq[tid]; sbk[tid]=bk[tid]; sbv[tid]=bv[tid]; }
    __syncthreads();

    const int w    = tid >> 5;
    const int lane = tid & 31;
    const int t    = (lane < 30) ? lane : 0;
    const bool act = (lane < 30);
    const int smp  = blockIdx.x * 8 + w;

    // ---- coalesced stage of x (420 floats = 105 float4) ----
    {
        const float4* xp = reinterpret_cast<const float4*>(x + (size_t)smp * 420);
        float4* sp = reinterpret_cast<float4*>(scr[w]);
        #pragma unroll
        for (int i = lane; i < 105; i += 32) sp[i] = xp[i];
    }
    __syncwarp();
    float xr[14];
    #pragma unroll
    for (int d = 0; d < 14; d++) xr[d] = scr[w][t*14 + d];
    __syncwarp();   // scr reads done; free to reuse below

    // ---- Conv1d embed (kernel 3, zero pad) via shuffles ----
    float xe[14];
    {
        float xm[14], xp2[14];
        #pragma unroll
        for (int d = 0; d < 14; d++) {
            float up = __shfl_up_sync(FULL, xr[d], 1);
            float dn = __shfl_down_sync(FULL, xr[d], 1);
            xm[d]  = (lane > 0)  ? up : 0.f;
            xp2[d] = (lane < 29) ? dn : 0.f;
        }
        #pragma unroll
        for (int o = 0; o < 14; o++) {
            float acc = sbe[o];
            #pragma unroll
            for (int ci = 0; ci < 14; ci++) {
                acc += sWe[o*42 + ci*3 + 0] * xm[ci];
                acc += sWe[o*42 + ci*3 + 1] * xr[ci];
                acc += sWe[o*42 + ci*3 + 2] * xp2[ci];
            }
            xe[o] = acc;
        }
    }

    // ---- QKV (E=1 per head) ----
    float q[8], k[8], v[8];
    #pragma unroll
    for (int h = 0; h < 8; h++) { q[h]=sbq[h]; k[h]=sbk[h]; v[h]=sbv[h]; }
    #pragma unroll
    for (int d = 0; d < 14; d++) {
        float xv = xe[d];
        #pragma unroll
        for (int h = 0; h < 8; h++) {
            q[h] += xv * sWq[d*8+h];
            k[h] += xv * sWk[d*8+h];
            v[h] += xv * sWv[d*8+h];
        }
    }
    float* qs = &scr[w][0];     // [h*32 + t]
    float* ks = &scr[w][256];
    if (act) {
        #pragma unroll
        for (int h = 0; h < 8; h++) { qs[h*32 + t] = q[h]; ks[h*32 + t] = k[h]; }
    }
    __syncwarp();

    // ---- circular correlation: corr[tau] = sum_{t,h} q[t][h]*k[(t-tau)%30][h]
    //      lane = tau; 8 independent accumulators (per head) for ILP ----
    float mv;
    {
        float acc[8] = {};
        #pragma unroll
        for (int tq = 0; tq < 30; tq++) {
            int src = tq - t; if (src < 0) src += 30;
            #pragma unroll
            for (int h = 0; h < 8; h++)
                acc[h] += qs[h*32 + tq] * ks[h*32 + src];
        }
        float s = ((acc[0]+acc[1]) + (acc[2]+acc[3])) + ((acc[4]+acc[5]) + (acc[6]+acc[7]));
        mv = act ? s * 0.125f : -1e30f;
    }

    // ---- top-3 via 3 warp butterfly (value,index) max reductions,
    //      first-index tie-break (matches lax.top_k) ----
    float wv0, wv1, wv2; int dl0, dl1, dl2;
    {
        float mrun = mv;
        #pragma unroll
        for (int p = 0; p < 3; p++) {
            float bv = mrun; int bi = lane;
            #pragma unroll
            for (int off = 16; off; off >>= 1) {
                float vo = __shfl_xor_sync(FULL, bv, off);
                int   io = __shfl_xor_sync(FULL, bi, off);
                if (vo > bv || (vo == bv && io < bi)) { bv = vo; bi = io; }
            }
            if (p == 0) { wv0 = bv; dl0 = bi; }
            else if (p == 1) { wv1 = bv; dl1 = bi; }
            else { wv2 = bv; dl2 = bi; }
            if (lane == bi) mrun = -1e30f;
        }
    }
    // softmax over (wv0 >= wv1 >= wv2)
    float e1 = expf(wv1 - wv0);
    float e2 = expf(wv2 - wv0);
    float inv = 1.f / (1.f + e1 + e2);
    float w0 = inv, w1 = e1 * inv, w2 = e2 * inv;

    // ---- delay aggregation via shuffles ----
    float agg[8];
    {
        int s0 = t + dl0; if (s0 >= 30) s0 -= 30;
        int s1 = t + dl1; if (s1 >= 30) s1 -= 30;
        int s2 = t + dl2; if (s2 >= 30) s2 -= 30;
        #pragma unroll
        for (int h = 0; h < 8; h++) {
            float a = w0 * __shfl_sync(FULL, v[h], s0);
            a      += w1 * __shfl_sync(FULL, v[h], s1);
            a      += w2 * __shfl_sync(FULL, v[h], s2);
            agg[h] = a;
        }
    }

    // ---- x1 = xe + agg @ Wo + bo ----
    float x1[14];
    #pragma unroll
    for (int d = 0; d < 14; d++) {
        float a = xe[d] + sbo[d];
        #pragma unroll
        for (int h = 0; h < 8; h++) a += agg[h] * sWo[h*14 + d];
        x1[d] = a;
    }

    // ---- series_decomp 1 via shuffle cumsum (replicate-pad MA-25) ----
    {
        const float fc0  = (t < 12) ? (float)(12 - t) : 0.f;
        const float fc29 = (t > 17) ? (float)(t - 17) : 0.f;
        const int hi   = (t + 12 > 29) ? 29 : t + 12;
        const int lom1 = t - 13;
        const int loix = (lom1 < 0) ? 0 : lom1;
        float* xo = g_xd + (size_t)smp * 420;
        #pragma unroll
        for (int d = 0; d < 14; d++) {
            float val = x1[d];
            float cs = val;
            #pragma unroll
            for (int off = 1; off < 32; off <<= 1) {
                float o = __shfl_up_sync(FULL, cs, off);
                if (lane >= off) cs += o;
            }
            float cshi = __shfl_sync(FULL, cs, hi);
            float cslo = __shfl_sync(FULL, cs, loix);
            float ssum = cshi - ((lom1 >= 0) ? cslo : 0.f);
            float x0  = __shfl_sync(FULL, val, 0);
            float x29 = __shfl_sync(FULL, val, 29);
            float mean = (ssum + fc0 * x0 + fc29 * x29) * (1.f / 25.f);
            if (act) xo[d*30 + t] = val - mean;   // channel-major, coalesced
        }
    }
}

// ============================================================================
// Kernel A2: FFN + decomp2 + LN + DyConv + adjacency -> g_f
// ============================================================================
__global__ __launch_bounds__(256) void kA2(
    const float* __restrict__ Wff1, const float* __restrict__ Wff2,
    const float* __restrict__ gnorm, const float* __restrict__ bnorm,
    const float* __restrict__ Wdy, const float* __restrict__ bdy,
    const float* __restrict__ channels)
{
    __shared__ float sF1[700], sF2[700];
    __shared__ float sg[14], sb[14];
    __shared__ float sWdy[900], sbdy[30];
    __shared__ float sAdj[196];
    __shared__ float x3s[8][424];

    const int tid = threadIdx.x;
    for (int i = tid; i < 700; i += 256) { sF1[i]=Wff1[i]; sF2[i]=Wff2[i]; }
    for (int i = tid; i < 900; i += 256) sWdy[i] = Wdy[i];
    if (tid < 30) sbdy[tid] = bdy[tid];
    if (tid < 14) { sg[tid]=gnorm[tid]; sb[tid]=bnorm[tid]; }
    if (tid < 14) {
        const float* row = channels + tid * 14;
        float mx = -1e30f;
        #pragma unroll
        for (int j = 0; j < 14; j++) mx = fmaxf(mx, row[j]);
        float s = 0.f;
        #pragma unroll
        for (int j = 0; j < 14; j++) s += expf(row[j] - mx);
        float inv = 1.f / s;
        #pragma unroll
        for (int j = 0; j < 14; j++) sAdj[tid * 14 + j] = expf(row[j] - mx) * inv;
    }
    __syncthreads();

    const int w    = tid >> 5;
    const int lane = tid & 31;
    const int t    = (lane < 30) ? lane : 0;
    const bool act = (lane < 30);
    const int smp  = blockIdx.x * 8 + w;

    // ---- load xd (channel-major -> coalesced) ----
    float xd[14];
    {
        const float* p = g_xd + (size_t)smp * 420;
        #pragma unroll
        for (int d = 0; d < 14; d++) xd[d] = p[d*30 + t];
    }

    // ---- FFN: x2 = xd + gelu_exact(xd @ F1) @ F2 ----
    float x2[14];
    {
        float y[14];
        #pragma unroll
        for (int d = 0; d < 14; d++) y[d] = 0.f;
        #pragma unroll 5
        for (int f = 0; f < 50; f++) {
            float hs = xd[0] * sF1[f];
            #pragma unroll
            for (int d = 1; d < 14; d++) hs += xd[d] * sF1[d*50 + f];
            float g = 0.5f * hs * (1.f + erff(hs * 0.70710678118654752f));
            #pragma unroll
            for (int d = 0; d < 14; d++) y[d] += g * sF2[f*14 + d];
        }
        #pragma unroll
        for (int d = 0; d < 14; d++) x2[d] = xd[d] + y[d];
    }

    // ---- series_decomp 2 ----
    float x3[14];
    {
        const float fc0  = (t < 12) ? (float)(12 - t) : 0.f;
        const float fc29 = (t > 17) ? (float)(t - 17) : 0.f;
        const int hi   = (t + 12 > 29) ? 29 : t + 12;
        const int lom1 = t - 13;
        const int loix = (lom1 < 0) ? 0 : lom1;
        #pragma unroll
        for (int d = 0; d < 14; d++) {
            float val = x2[d];
            float cs = val;
            #pragma unroll
            for (int off = 1; off < 32; off <<= 1) {
                float o = __shfl_up_sync(FULL, cs, off);
                if (lane >= off) cs += o;
            }
            float cshi = __shfl_sync(FULL, cs, hi);
            float cslo = __shfl_sync(FULL, cs, loix);
            float ssum = cshi - ((lom1 >= 0) ? cslo : 0.f);
            float x0  = __shfl_sync(FULL, val, 0);
            float x29 = __shfl_sync(FULL, val, 29);
            float mean = (ssum + fc0 * x0 + fc29 * x29) * (1.f / 25.f);
            x3[d] = val - mean;
        }
    }

    // ---- layernorm over 14 channels ----
    {
        float m = 0.f;
        #pragma unroll
        for (int d = 0; d < 14; d++) m += x3[d];
        m *= (1.f / 14.f);
        float var = 0.f;
        #pragma unroll
        for (int d = 0; d < 14; d++) { float dd = x3[d] - m; var += dd * dd; }
        var *= (1.f / 14.f);
        float inv = rsqrtf(var + 1e-5f);
        #pragma unroll
        for (int d = 0; d < 14; d++) x3[d] = (x3[d] - m) * inv * sg[d] + sb[d];
    }

    // ---- stage x3 rows to smem, then DyConv (lane = l) ----
    if (act) {
        #pragma unroll
        for (int d = 0; d < 14; d++) x3s[w][t*14 + d] = x3[d];
    }
    __syncwarp();
    float accd[14];
    {
        float bias = sbdy[t];
        #pragma unroll
        for (int d = 0; d < 14; d++) accd[d] = bias;
        #pragma unroll
        for (int m = 0; m < 30; m++) {
            float wm = sWdy[m*30 + t];
            #pragma unroll
            for (int d = 0; d < 14; d++) accd[d] += x3s[w][m*14 + d] * wm;
        }
    }

    // ---- dy = relu(adj @ h2) -> g_f ----
    {
        float* fo = g_f + (size_t)smp * 420;
        #pragma unroll
        for (int i = 0; i < 14; i++) {
            float a = 0.f;
            #pragma unroll
            for (int j = 0; j < 14; j++) a += sAdj[i*14 + j] * accd[j];
            if (act) fo[i*30 + t] = fmaxf(a, 0.f);
        }
    }
}

// ============================================================================
// Kernel B: hh = relu(f @ W1 + b1)   M=65536, K=420, N=256
// ============================================================================
__global__ __launch_bounds__(256) void kB(const float* __restrict__ W1,
                                          const float* __restrict__ b1)
{
    __shared__ float As[64][29];
    __shared__ __align__(16) float Bs[28][256];
    const int tid = threadIdx.x;
    const int m0 = (tid >> 5) * 8;
    const int n0 = (tid & 31) * 8;
    const size_t mbase = (size_t)blockIdx.x * 64;
    float acc[8][8] = {};

    for (int k0 = 0; k0 < 420; k0 += 28) {
        for (int idx = tid; idx < 64 * 28; idx += 256) {
            int m = idx / 28, kk = idx - m * 28;
            As[m][kk] = g_f[(mbase + m) * 420 + k0 + kk];
        }
        for (int idx = tid; idx < 28 * 64; idx += 256) {
            int r = idx / 64, c4 = idx - r * 64;
            reinterpret_cast<float4*>(Bs[r])[c4] =
                reinterpret_cast<const float4*>(W1 + (size_t)(k0 + r) * 256)[c4];
        }
        __syncthreads();
        #pragma unroll
        for (int kk = 0; kk < 28; kk++) {
            float a[8];
            #pragma unroll
            for (int i = 0; i < 8; i++) a[i] = As[m0 + i][kk];
            float4 bv0 = reinterpret_cast<const float4*>(&Bs[kk][n0])[0];
            float4 bv1 = reinterpret_cast<const float4*>(&Bs[kk][n0])[1];
            float b[8] = {bv0.x, bv0.y, bv0.z, bv0.w, bv1.x, bv1.y, bv1.z, bv1.w};
            #pragma unroll
            for (int i = 0; i < 8; i++)
                #pragma unroll
                for (int j = 0; j < 8; j++) acc[i][j] += a[i] * b[j];
        }
        __syncthreads();
    }
    float bb[8];
    #pragma unroll
    for (int j = 0; j < 8; j++) bb[j] = b1[n0 + j];
    #pragma unroll
    for (int i = 0; i < 8; i++) {
        float* o = g_hh + (mbase + m0 + i) * 256 + n0;
        #pragma unroll
        for (int j = 0; j < 8; j++) o[j] = fmaxf(acc[i][j] + bb[j], 0.f);
    }
}

// ============================================================================
// Kernel C: hr = [hh | f] @ [W2 ; Wres] + b2 + bres    M=65536, K=676, N=64
// ============================================================================
__global__ __launch_bounds__(256) void kC(const float* __restrict__ W2,
                                          const float* __restrict__ b2,
                                          const float* __restrict__ Wres,
                                          const float* __restrict__ bres)
{
    __shared__ float As[128][27];
    __shared__ __align__(16) float Bs[26][64];
    const int tid = threadIdx.x;
    const int m0 = (tid >> 4) * 8;
    const int n0 = (tid & 15) * 4;
    const size_t mbase = (size_t)blockIdx.x * 128;
    float acc[8][4] = {};

    for (int k0 = 0; k0 < 676; k0 += 26) {
        for (int idx = tid; idx < 128 * 26; idx += 256) {
            int m = idx / 26, kk = idx - m * 26;
            int k = k0 + kk;
            As[m][kk] = (k < 256) ? g_hh[(mbase + m) * 256 + k]
                                  : g_f [(mbase + m) * 420 + (k - 256)];
        }
        for (int idx = tid; idx < 26 * 64; idx += 256) {
            int r = idx / 64, c = idx - r * 64;
            int k = k0 + r;
            Bs[r][c] = (k < 256) ? W2[(size_t)k * 64 + c]
                                 : Wres[(size_t)(k - 256) * 64 + c];
        }
        __syncthreads();
        #pragma unroll
        for (int kk = 0; kk < 26; kk++) {
            float a[8];
            #pragma unroll
            for (int i = 0; i < 8; i++) a[i] = As[m0 + i][kk];
            float4 b4 = *reinterpret_cast<const float4*>(&Bs[kk][n0]);
            float b[4] = {b4.x, b4.y, b4.z, b4.w};
            #pragma unroll
            for (int i = 0; i < 8; i++)
                #pragma unroll
                for (int j = 0; j < 4; j++) acc[i][j] += a[i] * b[j];
        }
        __syncthreads();
    }
    float bb[4];
    #pragma unroll
    for (int j = 0; j < 4; j++) bb[j] = b2[n0 + j] + bres[n0 + j];
    #pragma unroll
    for (int i = 0; i < 8; i++) {
        float* o = g_hr + (mbase + m0 + i) * 64 + n0;
        #pragma unroll
        for (int j = 0; j < 4; j++) o[j] = acc[i][j] + bb[j];
    }
}

// ============================================================================
// Kernel D: out = LN64(hr) @ W3 + b3   (one warp per sample)
// ============================================================================
__global__ __launch_bounds__(256) void kD(const float* __restrict__ g_ln,
                                          const float* __restrict__ b_ln,
                                          const float* __restrict__ W3,
                                          const float* __restrict__ b3,
                                          float* __restrict__ out)
{
    int w = threadIdx.x >> 5, lane = threadIdx.x & 31;
    size_t s = (size_t)blockIdx.x * 8 + w;
    const float* r = g_hr + s * 64;
    float v0 = r[lane], v1 = r[lane + 32];
    float sum = v0 + v1, sq = v0 * v0 + v1 * v1;
    #pragma unroll
    for (int o = 16; o; o >>= 1) {
        sum += __shfl_xor_sync(FULL, sum, o);
        sq  += __shfl_xor_sync(FULL, sq,  o);
    }
    float m = sum * (1.f / 64.f);
    float var = sq * (1.f / 64.f) - m * m;
    float inv = rsqrtf(var + 1e-5f);
    float y0 = (v0 - m) * inv * g_ln[lane]      + b_ln[lane];
    float y1 = (v1 - m) * inv * g_ln[lane + 32] + b_ln[lane + 32];
    float d = y0 * W3[lane] + y1 * W3[lane + 32];
    #pragma unroll
    for (int o = 16; o; o >>= 1) d += __shfl_xor_sync(FULL, d, o);
    if (lane == 0) out[s] = d + b3[0];
}

// ============================================================================
extern "C" void kernel_launch(void* const* d_in, const int* in_sizes, int n_in,
                              void* d_out, int out_size)
{
    (void)in_sizes; (void)n_in; (void)out_size;
    const float* x = (const float*)d_in[0];

    kA1<<<BATCH / 8, 256>>>(x,
        (const float*)d_in[1],  (const float*)d_in[2],
        (const float*)d_in[3],  (const float*)d_in[4],
        (const float*)d_in[5],  (const float*)d_in[6],
        (const float*)d_in[7],  (const float*)d_in[8],
        (const float*)d_in[9],  (const float*)d_in[10]);

    kA2<<<BATCH / 8, 256>>>(
        (const float*)d_in[11], (const float*)d_in[12],
        (const float*)d_in[13], (const float*)d_in[14],
        (const float*)d_in[15], (const float*)d_in[16],
        (const float*)d_in[17]);

    kB<<<BATCH / 64, 256>>>((const float*)d_in[18], (const float*)d_in[19]);

    kC<<<BATCH / 128, 256>>>((const float*)d_in[20], (const float*)d_in[21],
                             (const float*)d_in[22], (const float*)d_in[23]);

    kD<<<BATCH / 8, 256>>>((const float*)d_in[24], (const float*)d_in[25],
                           (const float*)d_in[26], (const float*)d_in[27],
                           (float*)d_out);
}

// round 6
// speedup vs baseline: 1.4916x; 1.4916x over previous
#include <cuda_runtime.h>
#include <math.h>

#define BATCH 65536
#define FULL 0xffffffffu

// -------- device scratch (allocation-free rule: __device__ globals) --------
__device__ float g_f [(size_t)BATCH * 420];   // DyConv output
__device__ float g_hh[(size_t)BATCH * 256];   // relu(f@W1+b1)
__device__ float g_hr[(size_t)BATCH * 64];    // hh@W2 + f@Wres + b2 + bres

// ---------------- tf32 helpers (3xTF32 compensated GEMM) ----------------
__device__ __forceinline__ void split_tf32(float x, unsigned& hi, unsigned& lo) {
    asm("cvt.rna.tf32.f32 %0, %1;" : "=r"(hi) : "f"(x));
    float r = x - __uint_as_float(hi);
    asm("cvt.rna.tf32.f32 %0, %1;" : "=r"(lo) : "f"(r));
}
__device__ __forceinline__ void mma_tf32(float* c, const unsigned* a, const unsigned* b) {
    asm volatile(
        "mma.sync.aligned.m16n8k8.row.col.f32.tf32.tf32.f32 "
        "{%0,%1,%2,%3},{%4,%5,%6,%7},{%8,%9},{%0,%1,%2,%3};"
        : "+f"(c[0]), "+f"(c[1]), "+f"(c[2]), "+f"(c[3])
        : "r"(a[0]), "r"(a[1]), "r"(a[2]), "r"(a[3]), "r"(b[0]), "r"(b[1]));
}

// ============================================================================
// Kernel A: register-resident per-sample pipeline (R3 version).
// 1 warp = 1 sample, lane t in [0,30) holds the 14-channel row in registers.
// ============================================================================
__global__ __launch_bounds__(256) void kA(
    const float* __restrict__ x,
    const float* __restrict__ W_emb, const float* __restrict__ b_emb,
    const float* __restrict__ Wq, const float* __restrict__ bq,
    const float* __restrict__ Wk, const float* __restrict__ bk,
    const float* __restrict__ Wv, const float* __restrict__ bv,
    const float* __restrict__ Wo, const float* __restrict__ bo,
    const float* __restrict__ Wff1, const float* __restrict__ Wff2,
    const float* __restrict__ gnorm, const float* __restrict__ bnorm,
    const float* __restrict__ Wdy, const float* __restrict__ bdy,
    const float* __restrict__ channels)
{
    __shared__ float sWe[588], sbe[14];
    __shared__ float sWq[112], sWk[112], sWv[112];
    __shared__ float sbq[8], sbk[8], sbv[8];
    __shared__ float sWo[112], sbo[14];
    __shared__ float sF1[700], sF2[700];
    __shared__ float sg[14], sb[14];
    __shared__ float sWdy[900], sbdy[30];
    __shared__ float sAdj[196];
    __shared__ __align__(16) float scr[8][512];

    const int tid = threadIdx.x;
    for (int i = tid; i < 588; i += 256) sWe[i] = W_emb[i];
    for (int i = tid; i < 112; i += 256) { sWq[i]=Wq[i]; sWk[i]=Wk[i]; sWv[i]=Wv[i]; sWo[i]=Wo[i]; }
    for (int i = tid; i < 700; i += 256) { sF1[i]=Wff1[i]; sF2[i]=Wff2[i]; }
    for (int i = tid; i < 900; i += 256) sWdy[i] = Wdy[i];
    if (tid < 30) sbdy[tid] = bdy[tid];
    if (tid < 14) { sbe[tid]=b_emb[tid]; sbo[tid]=bo[tid]; sg[tid]=gnorm[tid]; sb[tid]=bnorm[tid]; }
    if (tid < 8)  { sbq[tid]=bq[tid]; sbk[tid]=bk[tid]; sbv[tid]=bv[tid]; }
    if (tid < 14) {
        const float* row = channels + tid * 14;
        float mx = -1e30f;
        #pragma unroll
        for (int j = 0; j < 14; j++) mx = fmaxf(mx, row[j]);
        float s = 0.f;
        #pragma unroll
        for (int j = 0; j < 14; j++) s += expf(row[j] - mx);
        float inv = 1.f / s;
        #pragma unroll
        for (int j = 0; j < 14; j++) sAdj[tid * 14 + j] = expf(row[j] - mx) * inv;
    }
    __syncthreads();

    const int w    = tid >> 5;
    const int lane = tid & 31;
    const int t    = (lane < 30) ? lane : 0;
    const bool act = (lane < 30);
    const int smp  = blockIdx.x * 8 + w;
    float* qs = &scr[w][0];
    float* ks = &scr[w][256];
    float* x3s = &scr[w][0];

    // ---- coalesced stage of x ----
    {
        const float4* xp = reinterpret_cast<const float4*>(x + (size_t)smp * 420);
        float4* sp = reinterpret_cast<float4*>(scr[w]);
        #pragma unroll
        for (int i = lane; i < 105; i += 32) sp[i] = xp[i];
    }
    __syncwarp();
    float xr[14];
    #pragma unroll
    for (int d = 0; d < 14; d++) xr[d] = scr[w][t*14 + d];
    __syncwarp();

    // ---- Conv1d embed via shuffles ----
    float xe[14];
    {
        float xm[14], xp2[14];
        #pragma unroll
        for (int d = 0; d < 14; d++) {
            float up = __shfl_up_sync(FULL, xr[d], 1);
            float dn = __shfl_down_sync(FULL, xr[d], 1);
            xm[d]  = (lane > 0)  ? up : 0.f;
            xp2[d] = (lane < 29) ? dn : 0.f;
        }
        #pragma unroll
        for (int o = 0; o < 14; o++) {
            float acc = sbe[o];
            #pragma unroll
            for (int ci = 0; ci < 14; ci++) {
                acc += sWe[o*42 + ci*3 + 0] * xm[ci];
                acc += sWe[o*42 + ci*3 + 1] * xr[ci];
                acc += sWe[o*42 + ci*3 + 2] * xp2[ci];
            }
            xe[o] = acc;
        }
    }

    // ---- QKV ----
    float q[8], k[8], v[8];
    #pragma unroll
    for (int h = 0; h < 8; h++) { q[h]=sbq[h]; k[h]=sbk[h]; v[h]=sbv[h]; }
    #pragma unroll
    for (int d = 0; d < 14; d++) {
        float xv = xe[d];
        #pragma unroll
        for (int h = 0; h < 8; h++) {
            q[h] += xv * sWq[d*8+h];
            k[h] += xv * sWk[d*8+h];
            v[h] += xv * sWv[d*8+h];
        }
    }
    if (act) {
        #pragma unroll
        for (int h = 0; h < 8; h++) { qs[h*32 + t] = q[h]; ks[h*32 + t] = k[h]; }
    }
    __syncwarp();

    // ---- circular correlation (8 independent accumulators) ----
    float mv;
    {
        float acc[8] = {};
        #pragma unroll
        for (int tq = 0; tq < 30; tq++) {
            int src = tq - t; if (src < 0) src += 30;
            #pragma unroll
            for (int h = 0; h < 8; h++)
                acc[h] += qs[h*32 + tq] * ks[h*32 + src];
        }
        float s = ((acc[0]+acc[1]) + (acc[2]+acc[3])) + ((acc[4]+acc[5]) + (acc[6]+acc[7]));
        mv = act ? s * 0.125f : -1e30f;
    }

    // ---- warp-parallel top-3 with first-index tie-break ----
    float wv0, wv1, wv2; int dl0, dl1, dl2;
    {
        float mrun = mv;
        #pragma unroll
        for (int p = 0; p < 3; p++) {
            float bv = mrun; int bi = lane;
            #pragma unroll
            for (int off = 16; off; off >>= 1) {
                float vo = __shfl_xor_sync(FULL, bv, off);
                int   io = __shfl_xor_sync(FULL, bi, off);
                if (vo > bv || (vo == bv && io < bi)) { bv = vo; bi = io; }
            }
            if (p == 0) { wv0 = bv; dl0 = bi; }
            else if (p == 1) { wv1 = bv; dl1 = bi; }
            else { wv2 = bv; dl2 = bi; }
            if (lane == bi) mrun = -1e30f;
        }
    }
    float e1 = expf(wv1 - wv0);
    float e2 = expf(wv2 - wv0);
    float inv = 1.f / (1.f + e1 + e2);
    float w0 = inv, w1 = e1 * inv, w2 = e2 * inv;

    // ---- delay aggregation ----
    float agg[8];
    {
        int s0 = t + dl0; if (s0 >= 30) s0 -= 30;
        int s1 = t + dl1; if (s1 >= 30) s1 -= 30;
        int s2 = t + dl2; if (s2 >= 30) s2 -= 30;
        #pragma unroll
        for (int h = 0; h < 8; h++) {
            float a = w0 * __shfl_sync(FULL, v[h], s0);
            a      += w1 * __shfl_sync(FULL, v[h], s1);
            a      += w2 * __shfl_sync(FULL, v[h], s2);
            agg[h] = a;
        }
    }

    // ---- x1 = xe + agg @ Wo + bo ----
    float x1[14];
    #pragma unroll
    for (int d = 0; d < 14; d++) {
        float a = xe[d] + sbo[d];
        #pragma unroll
        for (int h = 0; h < 8; h++) a += agg[h] * sWo[h*14 + d];
        x1[d] = a;
    }

    // ---- series_decomp 1 ----
    float xd[14];
    {
        const float fc0  = (t < 12) ? (float)(12 - t) : 0.f;
        const float fc29 = (t > 17) ? (float)(t - 17) : 0.f;
        const int hi   = (t + 12 > 29) ? 29 : t + 12;
        const int lom1 = t - 13;
        const int loix = (lom1 < 0) ? 0 : lom1;
        #pragma unroll
        for (int d = 0; d < 14; d++) {
            float val = x1[d];
            float cs = val;
            #pragma unroll
            for (int off = 1; off < 32; off <<= 1) {
                float o = __shfl_up_sync(FULL, cs, off);
                if (lane >= off) cs += o;
            }
            float cshi = __shfl_sync(FULL, cs, hi);
            float cslo = __shfl_sync(FULL, cs, loix);
            float ssum = cshi - ((lom1 >= 0) ? cslo : 0.f);
            float x0  = __shfl_sync(FULL, val, 0);
            float x29 = __shfl_sync(FULL, val, 29);
            float mean = (ssum + fc0 * x0 + fc29 * x29) * (1.f / 25.f);
            xd[d] = x1[d] - mean;
        }
    }

    // ---- FFN ----
    float x2[14];
    {
        float y[14];
        #pragma unroll
        for (int d = 0; d < 14; d++) y[d] = 0.f;
        #pragma unroll 5
        for (int f = 0; f < 50; f++) {
            float hs = xd[0] * sF1[f];
            #pragma unroll
            for (int d = 1; d < 14; d++) hs += xd[d] * sF1[d*50 + f];
            float g = 0.5f * hs * (1.f + erff(hs * 0.70710678118654752f));
            #pragma unroll
            for (int d = 0; d < 14; d++) y[d] += g * sF2[f*14 + d];
        }
        #pragma unroll
        for (int d = 0; d < 14; d++) x2[d] = xd[d] + y[d];
    }

    // ---- series_decomp 2 ----
    float x3[14];
    {
        const float fc0  = (t < 12) ? (float)(12 - t) : 0.f;
        const float fc29 = (t > 17) ? (float)(t - 17) : 0.f;
        const int hi   = (t + 12 > 29) ? 29 : t + 12;
        const int lom1 = t - 13;
        const int loix = (lom1 < 0) ? 0 : lom1;
        #pragma unroll
        for (int d = 0; d < 14; d++) {
            float val = x2[d];
            float cs = val;
            #pragma unroll
            for (int off = 1; off < 32; off <<= 1) {
                float o = __shfl_up_sync(FULL, cs, off);
                if (lane >= off) cs += o;
            }
            float cshi = __shfl_sync(FULL, cs, hi);
            float cslo = __shfl_sync(FULL, cs, loix);
            float ssum = cshi - ((lom1 >= 0) ? cslo : 0.f);
            float x0  = __shfl_sync(FULL, val, 0);
            float x29 = __shfl_sync(FULL, val, 29);
            float mean = (ssum + fc0 * x0 + fc29 * x29) * (1.f / 25.f);
            x3[d] = val - mean;
        }
    }

    // ---- layernorm over 14 channels ----
    {
        float m = 0.f;
        #pragma unroll
        for (int d = 0; d < 14; d++) m += x3[d];
        m *= (1.f / 14.f);
        float var = 0.f;
        #pragma unroll
        for (int d = 0; d < 14; d++) { float dd = x3[d] - m; var += dd * dd; }
        var *= (1.f / 14.f);
        float invs = rsqrtf(var + 1e-5f);
        #pragma unroll
        for (int d = 0; d < 14; d++) x3[d] = (x3[d] - m) * invs * sg[d] + sb[d];
    }

    // ---- DyConv ----
    __syncwarp();
    if (act) {
        #pragma unroll
        for (int d = 0; d < 14; d++) x3s[t*14 + d] = x3[d];
    }
    __syncwarp();
    float accd[14];
    {
        float bias = sbdy[t];
        #pragma unroll
        for (int d = 0; d < 14; d++) accd[d] = bias;
        #pragma unroll
        for (int m = 0; m < 30; m++) {
            float wm = sWdy[m*30 + t];
            #pragma unroll
            for (int d = 0; d < 14; d++) accd[d] += x3s[m*14 + d] * wm;
        }
    }

    // ---- dy = relu(adj @ h2) -> g_f ----
    {
        float* fo = g_f + (size_t)smp * 420;
        #pragma unroll
        for (int i = 0; i < 14; i++) {
            float a = 0.f;
            #pragma unroll
            for (int j = 0; j < 14; j++) a += sAdj[i*14 + j] * accd[j];
            if (act) fo[i*30 + t] = fmaxf(a, 0.f);
        }
    }
}

// ============================================================================
// Kernel B (tensor): hh = relu(f @ W1 + b1)  M=65536, K=420, N=256
// 3xTF32 mma.m16n8k8. BM=128, BN=64 (grid.y=4), BK=32, 8 warps (4m x 2n).
// ============================================================================
__global__ __launch_bounds__(256) void kB(const float* __restrict__ W1,
                                          const float* __restrict__ b1)
{
    __shared__ __align__(16) float As[128][36];
    __shared__ __align__(16) float Bs[64][36];
    const int tid = threadIdx.x;
    const int lane = tid & 31, wid = tid >> 5;
    const int wm = wid >> 1, wn = wid & 1;
    const size_t mbase = (size_t)blockIdx.x * 128;
    const int nbase = blockIdx.y * 64;
    float c[2][4][4] = {};

    for (int k0 = 0; k0 < 448; k0 += 32) {
        // A: 128 rows x 32 cols of g_f (zero-pad past 420)
        {
            int m = tid >> 1;
            const float4* gr = reinterpret_cast<const float4*>(g_f + (mbase + m) * 420);
            #pragma unroll
            for (int i = 0; i < 4; i++) {
                int qf = (tid & 1) * 4 + i;
                int kq = (k0 >> 2) + qf;
                float4 vv = (kq < 105) ? gr[kq] : make_float4(0.f,0.f,0.f,0.f);
                *reinterpret_cast<float4*>(&As[m][qf*4]) = vv;
            }
        }
        // B: W1 rows k0..k0+31, cols nbase..nbase+63, stored transposed Bs[n][k]
        {
            int kl = tid >> 3;
            int gk = k0 + kl;
            #pragma unroll
            for (int half = 0; half < 2; half++) {
                int n4 = ((tid & 7) + 8*half) * 4;
                float4 vv = make_float4(0.f,0.f,0.f,0.f);
                if (gk < 420)
                    vv = *reinterpret_cast<const float4*>(W1 + (size_t)gk*256 + nbase + n4);
                Bs[n4+0][kl] = vv.x; Bs[n4+1][kl] = vv.y;
                Bs[n4+2][kl] = vv.z; Bs[n4+3][kl] = vv.w;
            }
        }
        __syncthreads();
        #pragma unroll
        for (int ks = 0; ks < 4; ks++) {
            int kk = ks * 8;
            unsigned ah[2][4], al[2][4], bh[4][2], bl[4][2];
            #pragma unroll
            for (int mt = 0; mt < 2; mt++) {
                int r = wm*32 + mt*16 + (lane>>2);
                split_tf32(As[r  ][kk + (lane&3)    ], ah[mt][0], al[mt][0]);
                split_tf32(As[r+8][kk + (lane&3)    ], ah[mt][1], al[mt][1]);
                split_tf32(As[r  ][kk + (lane&3) + 4], ah[mt][2], al[mt][2]);
                split_tf32(As[r+8][kk + (lane&3) + 4], ah[mt][3], al[mt][3]);
            }
            #pragma unroll
            for (int nt = 0; nt < 4; nt++) {
                int nn = wn*32 + nt*8 + (lane>>2);
                split_tf32(Bs[nn][kk + (lane&3)    ], bh[nt][0], bl[nt][0]);
                split_tf32(Bs[nn][kk + (lane&3) + 4], bh[nt][1], bl[nt][1]);
            }
            #pragma unroll
            for (int mt = 0; mt < 2; mt++)
                #pragma unroll
                for (int nt = 0; nt < 4; nt++) {
                    mma_tf32(c[mt][nt], ah[mt], bh[nt]);
                    mma_tf32(c[mt][nt], ah[mt], bl[nt]);
                    mma_tf32(c[mt][nt], al[mt], bh[nt]);
                }
        }
        __syncthreads();
    }
    // epilogue: relu(+b1), float2 stores
    #pragma unroll
    for (int mt = 0; mt < 2; mt++) {
        int r0 = wm*32 + mt*16 + (lane>>2);
        #pragma unroll
        for (int nt = 0; nt < 4; nt++) {
            int cl = nbase + wn*32 + nt*8 + 2*(lane&3);
            float b0 = b1[cl], b1v = b1[cl+1];
            float2 lo = make_float2(fmaxf(c[mt][nt][0] + b0, 0.f), fmaxf(c[mt][nt][1] + b1v, 0.f));
            float2 hi = make_float2(fmaxf(c[mt][nt][2] + b0, 0.f), fmaxf(c[mt][nt][3] + b1v, 0.f));
            *reinterpret_cast<float2*>(g_hh + (mbase + r0    ) * 256 + cl) = lo;
            *reinterpret_cast<float2*>(g_hh + (mbase + r0 + 8) * 256 + cl) = hi;
        }
    }
}

// ============================================================================
// Kernel C (tensor): hr = [hh|f] @ [W2;Wres] + b2 + bres  M=65536, K=676, N=64
// Same structure as kB; K region split at 256.
// ============================================================================
__global__ __launch_bounds__(256) void kC(const float* __restrict__ W2,
                                          const float* __restrict__ b2,
                                          const float* __restrict__ Wres,
                                          const float* __restrict__ bres)
{
    __shared__ __align__(16) float As[128][36];
    __shared__ __align__(16) float Bs[64][36];
    const int tid = threadIdx.x;
    const int lane = tid & 31, wid = tid >> 5;
    const int wm = wid >> 1, wn = wid & 1;
    const size_t mbase = (size_t)blockIdx.x * 128;
    float c[2][4][4] = {};

    for (int k0 = 0; k0 < 704; k0 += 32) {
        // A: concat [hh(256) | f(420)]
        {
            int m = tid >> 1;
            const float* hrow = g_hh + (mbase + m) * 256;
            const float* frow = g_f  + (mbase + m) * 420;
            #pragma unroll
            for (int i = 0; i < 4; i++) {
                int qf = (tid & 1) * 4 + i;
                int gk = k0 + qf*4;
                float4 vv = make_float4(0.f,0.f,0.f,0.f);
                if (gk < 256) vv = *reinterpret_cast<const float4*>(hrow + gk);
                else { int kf = gk - 256; if (kf < 420) vv = *reinterpret_cast<const float4*>(frow + kf); }
                *reinterpret_cast<float4*>(&As[m][qf*4]) = vv;
            }
        }
        // B: concat [W2(256x64) ; Wres(420x64)], stored transposed
        {
            int kl = tid >> 3;
            int gk = k0 + kl;
            #pragma unroll
            for (int half = 0; half < 2; half++) {
                int n4 = ((tid & 7) + 8*half) * 4;
                float4 vv = make_float4(0.f,0.f,0.f,0.f);
                if (gk < 256) vv = *reinterpret_cast<const float4*>(W2 + (size_t)gk*64 + n4);
                else { int kf = gk - 256; if (kf < 420) vv = *reinterpret_cast<const float4*>(Wres + (size_t)kf*64 + n4); }
                Bs[n4+0][kl] = vv.x; Bs[n4+1][kl] = vv.y;
                Bs[n4+2][kl] = vv.z; Bs[n4+3][kl] = vv.w;
            }
        }
        __syncthreads();
        #pragma unroll
        for (int ks = 0; ks < 4; ks++) {
            int kk = ks * 8;
            unsigned ah[2][4], al[2][4], bh[4][2], bl[4][2];
            #pragma unroll
            for (int mt = 0; mt < 2; mt++) {
                int r = wm*32 + mt*16 + (lane>>2);
                split_tf32(As[r  ][kk + (lane&3)    ], ah[mt][0], al[mt][0]);
                split_tf32(As[r+8][kk + (lane&3)    ], ah[mt][1], al[mt][1]);
                split_tf32(As[r  ][kk + (lane&3) + 4], ah[mt][2], al[mt][2]);
                split_tf32(As[r+8][kk + (lane&3) + 4], ah[mt][3], al[mt][3]);
            }
            #pragma unroll
            for (int nt = 0; nt < 4; nt++) {
                int nn = wn*32 + nt*8 + (lane>>2);
                split_tf32(Bs[nn][kk + (lane&3)    ], bh[nt][0], bl[nt][0]);
                split_tf32(Bs[nn][kk + (lane&3) + 4], bh[nt][1], bl[nt][1]);
            }
            #pragma unroll
            for (int mt = 0; mt < 2; mt++)
                #pragma unroll
                for (int nt = 0; nt < 4; nt++) {
                    mma_tf32(c[mt][nt], ah[mt], bh[nt]);
                    mma_tf32(c[mt][nt], ah[mt], bl[nt]);
                    mma_tf32(c[mt][nt], al[mt], bh[nt]);
                }
        }
        __syncthreads();
    }
    #pragma unroll
    for (int mt = 0; mt < 2; mt++) {
        int r0 = wm*32 + mt*16 + (lane>>2);
        #pragma unroll
        for (int nt = 0; nt < 4; nt++) {
            int cl = wn*32 + nt*8 + 2*(lane&3);
            float b0 = b2[cl] + bres[cl], b1v = b2[cl+1] + bres[cl+1];
            float2 lo = make_float2(c[mt][nt][0] + b0, c[mt][nt][1] + b1v);
            float2 hi = make_float2(c[mt][nt][2] + b0, c[mt][nt][3] + b1v);
            *reinterpret_cast<float2*>(g_hr + (mbase + r0    ) * 64 + cl) = lo;
            *reinterpret_cast<float2*>(g_hr + (mbase + r0 + 8) * 64 + cl) = hi;
        }
    }
}

// ============================================================================
// Kernel D: out = LN64(hr) @ W3 + b3   (one warp per sample)
// ============================================================================
__global__ __launch_bounds__(256) void kD(const float* __restrict__ g_ln,
                                          const float* __restrict__ b_ln,
                                          const float* __restrict__ W3,
                                          const float* __restrict__ b3,
                                          float* __restrict__ out)
{
    int w = threadIdx.x >> 5, lane = threadIdx.x & 31;
    size_t s = (size_t)blockIdx.x * 8 + w;
    const float* r = g_hr + s * 64;
    float v0 = r[lane], v1 = r[lane + 32];
    float sum = v0 + v1, sq = v0 * v0 + v1 * v1;
    #pragma unroll
    for (int o = 16; o; o >>= 1) {
        sum += __shfl_xor_sync(FULL, sum, o);
        sq  += __shfl_xor_sync(FULL, sq,  o);
    }
    float m = sum * (1.f / 64.f);
    float var = sq * (1.f / 64.f) - m * m;
    float inv = rsqrtf(var + 1e-5f);
    float y0 = (v0 - m) * inv * g_ln[lane]      + b_ln[lane];
    float y1 = (v1 - m) * inv * g_ln[lane + 32] + b_ln[lane + 32];
    float d = y0 * W3[lane] + y1 * W3[lane + 32];
    #pragma unroll
    for (int o = 16; o; o >>= 1) d += __shfl_xor_sync(FULL, d, o);
    if (lane == 0) out[s] = d + b3[0];
}

// ============================================================================
extern "C" void kernel_launch(void* const* d_in, const int* in_sizes, int n_in,
                              void* d_out, int out_size)
{
    (void)in_sizes; (void)n_in; (void)out_size;
    const float* x = (const float*)d_in[0];

    kA<<<BATCH / 8, 256>>>(x,
        (const float*)d_in[1],  (const float*)d_in[2],
        (const float*)d_in[3],  (const float*)d_in[4],
        (const float*)d_in[5],  (const float*)d_in[6],
        (const float*)d_in[7],  (const float*)d_in[8],
        (const float*)d_in[9],  (const float*)d_in[10],
        (const float*)d_in[11], (const float*)d_in[12],
        (const float*)d_in[13], (const float*)d_in[14],
        (const float*)d_in[15], (const float*)d_in[16],
        (const float*)d_in[17]);

    kB<<<dim3(BATCH / 128, 4), 256>>>((const float*)d_in[18], (const float*)d_in[19]);

    kC<<<BATCH / 128, 256>>>((const float*)d_in[20], (const float*)d_in[21],
                             (const float*)d_in[22], (const float*)d_in[23]);

    kD<<<BATCH / 8, 256>>>((const float*)d_in[24], (const float*)d_in[25],
                           (const float*)d_in[26], (const float*)d_in[27],
                           (float*)d_out);
}

// round 7
// speedup vs baseline: 1.7050x; 1.1431x over previous
#include <cuda_runtime.h>
#include <math.h>

#define BATCH 65536
#define FULL 0xffffffffu

// -------- device scratch (allocation-free rule: __device__ globals) --------
__device__ float g_f [(size_t)BATCH * 420];   // DyConv output
__device__ float g_hh[(size_t)BATCH * 256];   // relu(f@W1+b1)
__device__ float g_hr[(size_t)BATCH * 64];    // hh@W2 + f@Wres + b2 + bres

// ---------------- packed f32x2 FMA (SASS FFMA2; ptxas never auto-fuses) ----
__device__ __forceinline__ float2 fma2(float2 a, float2 b, float2 c) {
    float2 r;
    asm("{\n\t"
        ".reg .b64 ra, rb, rc, rd;\n\t"
        "mov.b64 ra, {%2, %3};\n\t"
        "mov.b64 rb, {%4, %5};\n\t"
        "mov.b64 rc, {%6, %7};\n\t"
        "fma.rn.f32x2 rd, ra, rb, rc;\n\t"
        "mov.b64 {%0, %1}, rd;\n\t"
        "}"
        : "=f"(r.x), "=f"(r.y)
        : "f"(a.x), "f"(a.y), "f"(b.x), "f"(b.y), "f"(c.x), "f"(c.y));
    return r;
}

// ---------------- tf32 helpers (3xTF32 compensated GEMM) ----------------
__device__ __forceinline__ void split_tf32(float x, unsigned& hi, unsigned& lo) {
    asm("cvt.rna.tf32.f32 %0, %1;" : "=r"(hi) : "f"(x));
    float r = x - __uint_as_float(hi);
    asm("cvt.rna.tf32.f32 %0, %1;" : "=r"(lo) : "f"(r));
}
__device__ __forceinline__ void mma_tf32(float* c, const unsigned* a, const unsigned* b) {
    asm volatile(
        "mma.sync.aligned.m16n8k8.row.col.f32.tf32.tf32.f32 "
        "{%0,%1,%2,%3},{%4,%5,%6,%7},{%8,%9},{%0,%1,%2,%3};"
        : "+f"(c[0]), "+f"(c[1]), "+f"(c[2]), "+f"(c[3])
        : "r"(a[0]), "r"(a[1]), "r"(a[2]), "r"(a[3]), "r"(b[0]), "r"(b[1]));
}

// ============================================================================
// Kernel A: register-resident per-sample pipeline, f32x2-packed math.
// 1 warp = 1 sample, lane t in [0,30) holds the 14-channel row.
// ============================================================================
__global__ __launch_bounds__(256) void kA(
    const float* __restrict__ x,
    const float* __restrict__ W_emb, const float* __restrict__ b_emb,
    const float* __restrict__ Wq, const float* __restrict__ bq,
    const float* __restrict__ Wk, const float* __restrict__ bk,
    const float* __restrict__ Wv, const float* __restrict__ bv,
    const float* __restrict__ Wo, const float* __restrict__ bo,
    const float* __restrict__ Wff1, const float* __restrict__ Wff2,
    const float* __restrict__ gnorm, const float* __restrict__ bnorm,
    const float* __restrict__ Wdy, const float* __restrict__ bdy,
    const float* __restrict__ channels)
{
    // packed / aligned weight tiles
    __shared__ __align__(16) float2 sWe2[294];   // [(ci*3+tap)*7 + op] -> (W[2op], W[2op+1])
    __shared__ __align__(16) float  sbe[14];
    __shared__ __align__(16) float  sWq[112], sWk[112], sWv[112];   // [d*8+h], h-contig
    __shared__ __align__(16) float  sbq[8], sbk[8], sbv[8];
    __shared__ __align__(16) float  sWo[112];    // [h*14+d], d-contig
    __shared__ __align__(16) float  sbo[14];
    __shared__ __align__(16) float2 sF1t[350];   // [dp*50+f] -> (F1[2dp][f], F1[2dp+1][f])
    __shared__ __align__(16) float  sF2[700];    // [f*14+d], d-contig
    __shared__ __align__(16) float  sg[14], sb[14];
    __shared__ __align__(16) float  sWdy[900], sbdy[30];
    __shared__ __align__(16) float  sAdj[196];   // [i*14+j], j-contig
    __shared__ __align__(16) float  scr[8][512]; // per-warp: stage / qs2|ks2 / x3s2

    const int tid = threadIdx.x;
    for (int i = tid; i < 294; i += 256) {
        int ct = i / 7, op = i - ct * 7;
        sWe2[i] = make_float2(W_emb[(2*op)*42 + ct], W_emb[(2*op+1)*42 + ct]);
    }
    for (int i = tid; i < 112; i += 256) { sWq[i]=Wq[i]; sWk[i]=Wk[i]; sWv[i]=Wv[i]; sWo[i]=Wo[i]; }
    for (int i = tid; i < 350; i += 256) {
        int dp = i / 50, f = i - dp * 50;
        sF1t[i] = make_float2(Wff1[(2*dp)*50 + f], Wff1[(2*dp+1)*50 + f]);
    }
    for (int i = tid; i < 700; i += 256) sF2[i] = Wff2[i];
    for (int i = tid; i < 900; i += 256) sWdy[i] = Wdy[i];
    if (tid < 30) sbdy[tid] = bdy[tid];
    if (tid < 14) { sbe[tid]=b_emb[tid]; sbo[tid]=bo[tid]; sg[tid]=gnorm[tid]; sb[tid]=bnorm[tid]; }
    if (tid < 8)  { sbq[tid]=bq[tid]; sbk[tid]=bk[tid]; sbv[tid]=bv[tid]; }
    if (tid < 14) {
        const float* row = channels + tid * 14;
        float mx = -1e30f;
        #pragma unroll
        for (int j = 0; j < 14; j++) mx = fmaxf(mx, row[j]);
        float s = 0.f;
        #pragma unroll
        for (int j = 0; j < 14; j++) s += expf(row[j] - mx);
        float inv = 1.f / s;
        #pragma unroll
        for (int j = 0; j < 14; j++) sAdj[tid * 14 + j] = expf(row[j] - mx) * inv;
    }
    __syncthreads();

    const int w    = tid >> 5;
    const int lane = tid & 31;
    const int t    = (lane < 30) ? lane : 0;
    const bool act = (lane < 30);
    const int smp  = blockIdx.x * 8 + w;

    // ---- coalesced stage of x ----
    {
        const float4* xp = reinterpret_cast<const float4*>(x + (size_t)smp * 420);
        float4* sp = reinterpret_cast<float4*>(scr[w]);
        #pragma unroll
        for (int i = lane; i < 105; i += 32) sp[i] = xp[i];
    }
    __syncwarp();
    float xr[14];
    #pragma unroll
    for (int d = 0; d < 14; d++) xr[d] = scr[w][t*14 + d];
    __syncwarp();

    // ---- Conv1d embed (kernel 3, zero pad): packed over output-channel pairs ----
    float2 xe2[7];
    {
        const float2* sbe2 = reinterpret_cast<const float2*>(sbe);
        #pragma unroll
        for (int op = 0; op < 7; op++) xe2[op] = sbe2[op];
        #pragma unroll
        for (int ci = 0; ci < 14; ci++) {
            float up = __shfl_up_sync(FULL, xr[ci], 1);
            float dn = __shfl_down_sync(FULL, xr[ci], 1);
            float xm  = (lane > 0)  ? up : 0.f;
            float xp2 = (lane < 29) ? dn : 0.f;
            float tap[3] = { xm, xr[ci], xp2 };
            #pragma unroll
            for (int tp = 0; tp < 3; tp++) {
                float2 xv2 = make_float2(tap[tp], tap[tp]);
                const float2* wr = &sWe2[(ci*3 + tp) * 7];
                #pragma unroll
                for (int op = 0; op < 7; op++) xe2[op] = fma2(xv2, wr[op], xe2[op]);
            }
        }
    }

    // ---- QKV (packed over head pairs; Wq rows are h-contiguous) ----
    float2 q2[4], k2[4], v2[4];
    {
        const float2* bq2 = reinterpret_cast<const float2*>(sbq);
        const float2* bk2 = reinterpret_cast<const float2*>(sbk);
        const float2* bv2 = reinterpret_cast<const float2*>(sbv);
        #pragma unroll
        for (int hp = 0; hp < 4; hp++) { q2[hp]=bq2[hp]; k2[hp]=bk2[hp]; v2[hp]=bv2[hp]; }
        const float2* wq2 = reinterpret_cast<const float2*>(sWq);
        const float2* wk2 = reinterpret_cast<const float2*>(sWk);
        const float2* wv2 = reinterpret_cast<const float2*>(sWv);
        #pragma unroll
        for (int d = 0; d < 14; d++) {
            float xs = (d & 1) ? xe2[d>>1].y : xe2[d>>1].x;
            float2 xv2 = make_float2(xs, xs);
            #pragma unroll
            for (int hp = 0; hp < 4; hp++) {
                q2[hp] = fma2(xv2, wq2[d*4+hp], q2[hp]);
                k2[hp] = fma2(xv2, wk2[d*4+hp], k2[hp]);
                v2[hp] = fma2(xv2, wv2[d*4+hp], v2[hp]);
            }
        }
    }
    float v[8];
    #pragma unroll
    for (int hp = 0; hp < 4; hp++) { v[2*hp] = v2[hp].x; v[2*hp+1] = v2[hp].y; }

    // stage q,k packed: qs2[hp*32+t] | ks2[hp*32+t]
    float2* qs2 = reinterpret_cast<float2*>(&scr[w][0]);
    float2* ks2 = reinterpret_cast<float2*>(&scr[w][256]);
    if (act) {
        #pragma unroll
        for (int hp = 0; hp < 4; hp++) { qs2[hp*32 + t] = q2[hp]; ks2[hp*32 + t] = k2[hp]; }
    }
    __syncwarp();

    // ---- circular correlation corr[tau] = sum_{t,h} q[t][h]*k[(t-tau)%30][h] ----
    float mv;
    {
        float2 acc2[4] = {};
        #pragma unroll
        for (int tq = 0; tq < 30; tq++) {
            int src = tq - t; if (src < 0) src += 30;
            #pragma unroll
            for (int hp = 0; hp < 4; hp++)
                acc2[hp] = fma2(qs2[hp*32 + tq], ks2[hp*32 + src], acc2[hp]);
        }
        float s = ((acc2[0].x+acc2[0].y) + (acc2[1].x+acc2[1].y))
                + ((acc2[2].x+acc2[2].y) + (acc2[3].x+acc2[3].y));
        mv = act ? s * 0.125f : -1e30f;
    }

    // ---- warp-parallel top-3 with first-index tie-break ----
    float wv0, wv1, wv2; int dl0, dl1, dl2;
    {
        float mrun = mv;
        #pragma unroll
        for (int p = 0; p < 3; p++) {
            float bv = mrun; int bi = lane;
            #pragma unroll
            for (int off = 16; off; off >>= 1) {
                float vo = __shfl_xor_sync(FULL, bv, off);
                int   io = __shfl_xor_sync(FULL, bi, off);
                if (vo > bv || (vo == bv && io < bi)) { bv = vo; bi = io; }
            }
            if (p == 0) { wv0 = bv; dl0 = bi; }
            else if (p == 1) { wv1 = bv; dl1 = bi; }
            else { wv2 = bv; dl2 = bi; }
            if (lane == bi) mrun = -1e30f;
        }
    }
    float e1 = expf(wv1 - wv0);
    float e2 = expf(wv2 - wv0);
    float inv = 1.f / (1.f + e1 + e2);
    float w0 = inv, w1 = e1 * inv, w2 = e2 * inv;

    // ---- delay aggregation via shuffles ----
    float agg[8];
    {
        int s0 = t + dl0; if (s0 >= 30) s0 -= 30;
        int s1 = t + dl1; if (s1 >= 30) s1 -= 30;
        int s2 = t + dl2; if (s2 >= 30) s2 -= 30;
        #pragma unroll
        for (int h = 0; h < 8; h++) {
            float a = w0 * __shfl_sync(FULL, v[h], s0);
            a      += w1 * __shfl_sync(FULL, v[h], s1);
            a      += w2 * __shfl_sync(FULL, v[h], s2);
            agg[h] = a;
        }
    }

    // ---- x1 = xe + agg @ Wo + bo  (packed over channel pairs; Wo d-contig) ----
    float2 x1_2[7];
    {
        const float2* sbo2 = reinterpret_cast<const float2*>(sbo);
        #pragma unroll
        for (int dp = 0; dp < 7; dp++)
            x1_2[dp] = make_float2(xe2[dp].x + sbo2[dp].x, xe2[dp].y + sbo2[dp].y);
        #pragma unroll
        for (int h = 0; h < 8; h++) {
            float2 a2 = make_float2(agg[h], agg[h]);
            const float2* wo2 = reinterpret_cast<const float2*>(&sWo[h*14]);
            #pragma unroll
            for (int dp = 0; dp < 7; dp++) x1_2[dp] = fma2(a2, wo2[dp], x1_2[dp]);
        }
    }

    // ---- series_decomp 1 (shuffle cumsum, replicate-pad MA-25) ----
    const float fc0  = (t < 12) ? (float)(12 - t) : 0.f;
    const float fc29 = (t > 17) ? (float)(t - 17) : 0.f;
    const int hi   = (t + 12 > 29) ? 29 : t + 12;
    const int lom1 = t - 13;
    const int loix = (lom1 < 0) ? 0 : lom1;
    float2 xd2[7];
    #pragma unroll
    for (int dp = 0; dp < 7; dp++) {
        float2 val = x1_2[dp];
        float2 cs = val;
        #pragma unroll
        for (int off = 1; off < 32; off <<= 1) {
            float ox = __shfl_up_sync(FULL, cs.x, off);
            float oy = __shfl_up_sync(FULL, cs.y, off);
            if (lane >= off) { cs.x += ox; cs.y += oy; }
        }
        float shx = __shfl_sync(FULL, cs.x, hi),   shy = __shfl_sync(FULL, cs.y, hi);
        float slx = __shfl_sync(FULL, cs.x, loix), sly = __shfl_sync(FULL, cs.y, loix);
        float x0x = __shfl_sync(FULL, val.x, 0),   x0y = __shfl_sync(FULL, val.y, 0);
        float x9x = __shfl_sync(FULL, val.x, 29),  x9y = __shfl_sync(FULL, val.y, 29);
        float ssx = shx - ((lom1 >= 0) ? slx : 0.f);
        float ssy = shy - ((lom1 >= 0) ? sly : 0.f);
        xd2[dp].x = val.x - (ssx + fc0 * x0x + fc29 * x9x) * (1.f / 25.f);
        xd2[dp].y = val.y - (ssy + fc0 * x0y + fc29 * x9y) * (1.f / 25.f);
    }

    // ---- FFN: x2 = xd + gelu_exact(xd @ F1) @ F2  (packed dot + packed accum) ----
    float2 x2_2[7];
    {
        float2 y2[7] = {};
        #pragma unroll 5
        for (int f = 0; f < 50; f++) {
            float2 h2 = make_float2(0.f, 0.f);
            #pragma unroll
            for (int dp = 0; dp < 7; dp++) h2 = fma2(xd2[dp], sF1t[dp*50 + f], h2);
            float hs = h2.x + h2.y;
            float g = 0.5f * hs * (1.f + erff(hs * 0.70710678118654752f));
            float2 g2 = make_float2(g, g);
            const float2* f2r = reinterpret_cast<const float2*>(&sF2[f*14]);
            #pragma unroll
            for (int dp = 0; dp < 7; dp++) y2[dp] = fma2(g2, f2r[dp], y2[dp]);
        }
        #pragma unroll
        for (int dp = 0; dp < 7; dp++)
            x2_2[dp] = make_float2(xd2[dp].x + y2[dp].x, xd2[dp].y + y2[dp].y);
    }

    // ---- series_decomp 2 ----
    float2 x3_2[7];
    #pragma unroll
    for (int dp = 0; dp < 7; dp++) {
        float2 val = x2_2[dp];
        float2 cs = val;
        #pragma unroll
        for (int off = 1; off < 32; off <<= 1) {
            float ox = __shfl_up_sync(FULL, cs.x, off);
            float oy = __shfl_up_sync(FULL, cs.y, off);
            if (lane >= off) { cs.x += ox; cs.y += oy; }
        }
        float shx = __shfl_sync(FULL, cs.x, hi),   shy = __shfl_sync(FULL, cs.y, hi);
        float slx = __shfl_sync(FULL, cs.x, loix), sly = __shfl_sync(FULL, cs.y, loix);
        float x0x = __shfl_sync(FULL, val.x, 0),   x0y = __shfl_sync(FULL, val.y, 0);
        float x9x = __shfl_sync(FULL, val.x, 29),  x9y = __shfl_sync(FULL, val.y, 29);
        float ssx = shx - ((lom1 >= 0) ? slx : 0.f);
        float ssy = shy - ((lom1 >= 0) ? sly : 0.f);
        x3_2[dp].x = val.x - (ssx + fc0 * x0x + fc29 * x9x) * (1.f / 25.f);
        x3_2[dp].y = val.y - (ssy + fc0 * x0y + fc29 * x9y) * (1.f / 25.f);
    }

    // ---- layernorm over 14 channels ----
    {
        float m = 0.f;
        #pragma unroll
        for (int dp = 0; dp < 7; dp++) m += x3_2[dp].x + x3_2[dp].y;
        m *= (1.f / 14.f);
        float var = 0.f;
        #pragma unroll
        for (int dp = 0; dp < 7; dp++) {
            float dx = x3_2[dp].x - m, dy = x3_2[dp].y - m;
            var += dx * dx + dy * dy;
        }
        var *= (1.f / 14.f);
        float invs = rsqrtf(var + 1e-5f);
        const float2* g2 = reinterpret_cast<const float2*>(sg);
        const float2* b2 = reinterpret_cast<const float2*>(sb);
        #pragma unroll
        for (int dp = 0; dp < 7; dp++) {
            x3_2[dp].x = (x3_2[dp].x - m) * invs * g2[dp].x + b2[dp].x;
            x3_2[dp].y = (x3_2[dp].y - m) * invs * g2[dp].y + b2[dp].y;
        }
    }

    // ---- DyConv: stage x3 pairs, accumulate over m (lane = l) ----
    __syncwarp();                     // correlation reads of qs2/ks2 done
    float2* x3s2 = reinterpret_cast<float2*>(&scr[w][0]);  // [m*7+dp]
    if (act) {
        #pragma unroll
        for (int dp = 0; dp < 7; dp++) x3s2[t*7 + dp] = x3_2[dp];
    }
    __syncwarp();
    float2 accd2[7];
    {
        float bias = sbdy[t];
        #pragma unroll
        for (int dp = 0; dp < 7; dp++) accd2[dp] = make_float2(bias, bias);
        #pragma unroll
        for (int m = 0; m < 30; m++) {
            float wm = sWdy[m*30 + t];
            float2 wm2 = make_float2(wm, wm);
            #pragma unroll
            for (int dp = 0; dp < 7; dp++)
                accd2[dp] = fma2(x3s2[m*7 + dp], wm2, accd2[dp]);
        }
    }

    // ---- dy = relu(adj @ h2) -> g_f ----
    {
        float* fo = g_f + (size_t)smp * 420;
        #pragma unroll
        for (int i = 0; i < 14; i++) {
            const float2* ar = reinterpret_cast<const float2*>(&sAdj[i*14]);
            float2 a2 = make_float2(0.f, 0.f);
            #pragma unroll
            for (int jp = 0; jp < 7; jp++) a2 = fma2(ar[jp], accd2[jp], a2);
            float a = a2.x + a2.y;
            if (act) fo[i*30 + t] = fmaxf(a, 0.f);
        }
    }
}

// ============================================================================
// Kernel B (tensor): hh = relu(f @ W1 + b1)  M=65536, K=420, N=256
// 3xTF32 mma.m16n8k8. BM=128, BN=64 (grid.y=4), BK=32, 8 warps (4m x 2n).
// ============================================================================
__global__ __launch_bounds__(256) void kB(const float* __restrict__ W1,
                                          const float* __restrict__ b1)
{
    __shared__ __align__(16) float As[128][36];
    __shared__ __align__(16) float Bs[64][36];
    const int tid = threadIdx.x;
    const int lane = tid & 31, wid = tid >> 5;
    const int wm = wid >> 1, wn = wid & 1;
    const size_t mbase = (size_t)blockIdx.x * 128;
    const int nbase = blockIdx.y * 64;
    float c[2][4][4] = {};

    for (int k0 = 0; k0 < 448; k0 += 32) {
        {
            int m = tid >> 1;
            const float4* gr = reinterpret_cast<const float4*>(g_f + (mbase + m) * 420);
            #pragma unroll
            for (int i = 0; i < 4; i++) {
                int qf = (tid & 1) * 4 + i;
                int kq = (k0 >> 2) + qf;
                float4 vv = (kq < 105) ? gr[kq] : make_float4(0.f,0.f,0.f,0.f);
                *reinterpret_cast<float4*>(&As[m][qf*4]) = vv;
            }
        }
        {
            int kl = tid >> 3;
            int gk = k0 + kl;
            #pragma unroll
            for (int half = 0; half < 2; half++) {
                int n4 = ((tid & 7) + 8*half) * 4;
                float4 vv = make_float4(0.f,0.f,0.f,0.f);
                if (gk < 420)
                    vv = *reinterpret_cast<const float4*>(W1 + (size_t)gk*256 + nbase + n4);
                Bs[n4+0][kl] = vv.x; Bs[n4+1][kl] = vv.y;
                Bs[n4+2][kl] = vv.z; Bs[n4+3][kl] = vv.w;
            }
        }
        __syncthreads();
        #pragma unroll
        for (int ks = 0; ks < 4; ks++) {
            int kk = ks * 8;
            unsigned ah[2][4], al[2][4], bh[4][2], bl[4][2];
            #pragma unroll
            for (int mt = 0; mt < 2; mt++) {
                int r = wm*32 + mt*16 + (lane>>2);
                split_tf32(As[r  ][kk + (lane&3)    ], ah[mt][0], al[mt][0]);
                split_tf32(As[r+8][kk + (lane&3)    ], ah[mt][1], al[mt][1]);
                split_tf32(As[r  ][kk + (lane&3) + 4], ah[mt][2], al[mt][2]);
                split_tf32(As[r+8][kk + (lane&3) + 4], ah[mt][3], al[mt][3]);
            }
            #pragma unroll
            for (int nt = 0; nt < 4; nt++) {
                int nn = wn*32 + nt*8 + (lane>>2);
                split_tf32(Bs[nn][kk + (lane&3)    ], bh[nt][0], bl[nt][0]);
                split_tf32(Bs[nn][kk + (lane&3) + 4], bh[nt][1], bl[nt][1]);
            }
            #pragma unroll
            for (int mt = 0; mt < 2; mt++)
                #pragma unroll
                for (int nt = 0; nt < 4; nt++) {
                    mma_tf32(c[mt][nt], ah[mt], bh[nt]);
                    mma_tf32(c[mt][nt], ah[mt], bl[nt]);
                    mma_tf32(c[mt][nt], al[mt], bh[nt]);
                }
        }
        __syncthreads();
    }
    #pragma unroll
    for (int mt = 0; mt < 2; mt++) {
        int r0 = wm*32 + mt*16 + (lane>>2);
        #pragma unroll
        for (int nt = 0; nt < 4; nt++) {
            int cl = nbase + wn*32 + nt*8 + 2*(lane&3);
            float b0 = b1[cl], b1v = b1[cl+1];
            float2 lo = make_float2(fmaxf(c[mt][nt][0] + b0, 0.f), fmaxf(c[mt][nt][1] + b1v, 0.f));
            float2 hi = make_float2(fmaxf(c[mt][nt][2] + b0, 0.f), fmaxf(c[mt][nt][3] + b1v, 0.f));
            *reinterpret_cast<float2*>(g_hh + (mbase + r0    ) * 256 + cl) = lo;
            *reinterpret_cast<float2*>(g_hh + (mbase + r0 + 8) * 256 + cl) = hi;
        }
    }
}

// ============================================================================
// Kernel C (tensor): hr = [hh|f] @ [W2;Wres] + b2 + bres  M=65536, K=676, N=64
// ============================================================================
__global__ __launch_bounds__(256) void kC(const float* __restrict__ W2,
                                          const float* __restrict__ b2,
                                          const float* __restrict__ Wres,
                                          const float* __restrict__ bres)
{
    __shared__ __align__(16) float As[128][36];
    __shared__ __align__(16) float Bs[64][36];
    const int tid = threadIdx.x;
    const int lane = tid & 31, wid = tid >> 5;
    const int wm = wid >> 1, wn = wid & 1;
    const size_t mbase = (size_t)blockIdx.x * 128;
    float c[2][4][4] = {};

    for (int k0 = 0; k0 < 704; k0 += 32) {
        {
            int m = tid >> 1;
            const float* hrow = g_hh + (mbase + m) * 256;
            const float* frow = g_f  + (mbase + m) * 420;
            #pragma unroll
            for (int i = 0; i < 4; i++) {
                int qf = (tid & 1) * 4 + i;
                int gk = k0 + qf*4;
                float4 vv = make_float4(0.f,0.f,0.f,0.f);
                if (gk < 256) vv = *reinterpret_cast<const float4*>(hrow + gk);
                else { int kf = gk - 256; if (kf < 420) vv = *reinterpret_cast<const float4*>(frow + kf); }
                *reinterpret_cast<float4*>(&As[m][qf*4]) = vv;
            }
        }
        {
            int kl = tid >> 3;
            int gk = k0 + kl;
            #pragma unroll
            for (int half = 0; half < 2; half++) {
                int n4 = ((tid & 7) + 8*half) * 4;
                float4 vv = make_float4(0.f,0.f,0.f,0.f);
                if (gk < 256) vv = *reinterpret_cast<const float4*>(W2 + (size_t)gk*64 + n4);
                else { int kf = gk - 256; if (kf < 420) vv = *reinterpret_cast<const float4*>(Wres + (size_t)kf*64 + n4); }
                Bs[n4+0][kl] = vv.x; Bs[n4+1][kl] = vv.y;
                Bs[n4+2][kl] = vv.z; Bs[n4+3][kl] = vv.w;
            }
        }
        __syncthreads();
        #pragma unroll
        for (int ks = 0; ks < 4; ks++) {
            int kk = ks * 8;
            unsigned ah[2][4], al[2][4], bh[4][2], bl[4][2];
            #pragma unroll
            for (int mt = 0; mt < 2; mt++) {
                int r = wm*32 + mt*16 + (lane>>2);
                split_tf32(As[r  ][kk + (lane&3)    ], ah[mt][0], al[mt][0]);
                split_tf32(As[r+8][kk + (lane&3)    ], ah[mt][1], al[mt][1]);
                split_tf32(As[r  ][kk + (lane&3) + 4], ah[mt][2], al[mt][2]);
                split_tf32(As[r+8][kk + (lane&3) + 4], ah[mt][3], al[mt][3]);
            }
            #pragma unroll
            for (int nt = 0; nt < 4; nt++) {
                int nn = wn*32 + nt*8 + (lane>>2);
                split_tf32(Bs[nn][kk + (lane&3)    ], bh[nt][0], bl[nt][0]);
                split_tf32(Bs[nn][kk + (lane&3) + 4], bh[nt][1], bl[nt][1]);
            }
            #pragma unroll
            for (int mt = 0; mt < 2; mt++)
                #pragma unroll
                for (int nt = 0; nt < 4; nt++) {
                    mma_tf32(c[mt][nt], ah[mt], bh[nt]);
                    mma_tf32(c[mt][nt], ah[mt], bl[nt]);
                    mma_tf32(c[mt][nt], al[mt], bh[nt]);
                }
        }
        __syncthreads();
    }
    #pragma unroll
    for (int mt = 0; mt < 2; mt++) {
        int r0 = wm*32 + mt*16 + (lane>>2);
        #pragma unroll
        for (int nt = 0; nt < 4; nt++) {
            int cl = wn*32 + nt*8 + 2*(lane&3);
            float b0 = b2[cl] + bres[cl], b1v = b2[cl+1] + bres[cl+1];
            float2 lo = make_float2(c[mt][nt][0] + b0, c[mt][nt][1] + b1v);
            float2 hi = make_float2(c[mt][nt][2] + b0, c[mt][nt][3] + b1v);
            *reinterpret_cast<float2*>(g_hr + (mbase + r0    ) * 64 + cl) = lo;
            *reinterpret_cast<float2*>(g_hr + (mbase + r0 + 8) * 64 + cl) = hi;
        }
    }
}

// ============================================================================
// Kernel D: out = LN64(hr) @ W3 + b3   (one warp per sample)
// ============================================================================
__global__ __launch_bounds__(256) void kD(const float* __restrict__ g_ln,
                                          const float* __restrict__ b_ln,
                                          const float* __restrict__ W3,
                                          const float* __restrict__ b3,
                                          float* __restrict__ out)
{
    int w = threadIdx.x >> 5, lane = threadIdx.x & 31;
    size_t s = (size_t)blockIdx.x * 8 + w;
    const float* r = g_hr + s * 64;
    float v0 = r[lane], v1 = r[lane + 32];
    float sum = v0 + v1, sq = v0 * v0 + v1 * v1;
    #pragma unroll
    for (int o = 16; o; o >>= 1) {
        sum += __shfl_xor_sync(FULL, sum, o);
        sq  += __shfl_xor_sync(FULL, sq,  o);
    }
    float m = sum * (1.f / 64.f);
    float var = sq * (1.f / 64.f) - m * m;
    float inv = rsqrtf(var + 1e-5f);
    float y0 = (v0 - m) * inv * g_ln[lane]      + b_ln[lane];
    float y1 = (v1 - m) * inv * g_ln[lane + 32] + b_ln[lane + 32];
    float d = y0 * W3[lane] + y1 * W3[lane + 32];
    #pragma unroll
    for (int o = 16; o; o >>= 1) d += __shfl_xor_sync(FULL, d, o);
    if (lane == 0) out[s] = d + b3[0];
}

// ============================================================================
extern "C" void kernel_launch(void* const* d_in, const int* in_sizes, int n_in,
                              void* d_out, int out_size)
{
    (void)in_sizes; (void)n_in; (void)out_size;
    const float* x = (const float*)d_in[0];

    kA<<<BATCH / 8, 256>>>(x,
        (const float*)d_in[1],  (const float*)d_in[2],
        (const float*)d_in[3],  (const float*)d_in[4],
        (const float*)d_in[5],  (const float*)d_in[6],
        (const float*)d_in[7],  (const float*)d_in[8],
        (const float*)d_in[9],  (const float*)d_in[10],
        (const float*)d_in[11], (const float*)d_in[12],
        (const float*)d_in[13], (const float*)d_in[14],
        (const float*)d_in[15], (const float*)d_in[16],
        (const float*)d_in[17]);

    kB<<<dim3(BATCH / 128, 4), 256>>>((const float*)d_in[18], (const float*)d_in[19]);

    kC<<<BATCH / 128, 256>>>((const float*)d_in[20], (const float*)d_in[21],
                             (const float*)d_in[22], (const float*)d_in[23]);

    kD<<<BATCH / 8, 256>>>((const float*)d_in[24], (const float*)d_in[25],
                           (const float*)d_in[26], (const float*)d_in[27],
                           (float*)d_out);
}

// round 8
// speedup vs baseline: 1.7066x; 1.0009x over previous
#include <cuda_runtime.h>
#include <math.h>

#define BATCH 65536
#define FULL 0xffffffffu

typedef unsigned long long u64;

// -------- device scratch (allocation-free rule: __device__ globals) --------
__device__ float g_f [(size_t)BATCH * 420];   // DyConv output
__device__ float g_hh[(size_t)BATCH * 256];   // relu(f@W1+b1)
__device__ float g_hr[(size_t)BATCH * 64];    // hh@W2 + f@Wres + b2 + bres

// ---------------- packed f32x2 ops on b64 registers (no pack MOVs) --------
__device__ __forceinline__ u64 pack2(float x, float y) {
    u64 r; asm("mov.b64 %0, {%1, %2};" : "=l"(r) : "f"(x), "f"(y)); return r;
}
__device__ __forceinline__ u64 dup2(float s) { return pack2(s, s); }
__device__ __forceinline__ void unpack2(u64 v, float& x, float& y) {
    asm("mov.b64 {%0, %1}, %2;" : "=f"(x), "=f"(y) : "l"(v));
}
__device__ __forceinline__ u64 fma2u(u64 a, u64 b, u64 c) {
    u64 d; asm("fma.rn.f32x2 %0, %1, %2, %3;" : "=l"(d) : "l"(a), "l"(b), "l"(c)); return d;
}
__device__ __forceinline__ u64 add2u(u64 a, u64 b) {
    u64 d; asm("add.rn.f32x2 %0, %1, %2;" : "=l"(d) : "l"(a), "l"(b)); return d;
}

// ---------------- tf32 helpers (3xTF32 compensated GEMM) ----------------
__device__ __forceinline__ void split_tf32(float x, unsigned& hi, unsigned& lo) {
    asm("cvt.rna.tf32.f32 %0, %1;" : "=r"(hi) : "f"(x));
    float r = x - __uint_as_float(hi);
    asm("cvt.rna.tf32.f32 %0, %1;" : "=r"(lo) : "f"(r));
}
__device__ __forceinline__ void mma_tf32(float* c, const unsigned* a, const unsigned* b) {
    asm volatile(
        "mma.sync.aligned.m16n8k8.row.col.f32.tf32.tf32.f32 "
        "{%0,%1,%2,%3},{%4,%5,%6,%7},{%8,%9},{%0,%1,%2,%3};"
        : "+f"(c[0]), "+f"(c[1]), "+f"(c[2]), "+f"(c[3])
        : "r"(a[0]), "r"(a[1]), "r"(a[2]), "r"(a[3]), "r"(b[0]), "r"(b[1]));
}

// ---- shuffle-scan series_decomp helper (replicate-pad MA-25), scalar ----
__device__ __forceinline__ float decomp25(float val, int lane, int hi, int loix,
                                          int lom1, float fc0, float fc29) {
    float cs = val;
    #pragma unroll
    for (int off = 1; off < 32; off <<= 1) {
        float o = __shfl_up_sync(FULL, cs, off);
        if (lane >= off) cs += o;
    }
    float cshi = __shfl_sync(FULL, cs, hi);
    float cslo = __shfl_sync(FULL, cs, loix);
    float ssum = cshi - ((lom1 >= 0) ? cslo : 0.f);
    float x0  = __shfl_sync(FULL, val, 0);
    float x29 = __shfl_sync(FULL, val, 29);
    return val - (ssum + fc0 * x0 + fc29 * x29) * (1.f / 25.f);
}

// ============================================================================
// Kernel A: register-resident per-sample pipeline, b64-packed FFMA2 math.
// 1 warp = 1 sample, lane t in [0,30) holds the 14-channel row.
// ============================================================================
__global__ __launch_bounds__(256) void kA(
    const float* __restrict__ x,
    const float* __restrict__ W_emb, const float* __restrict__ b_emb,
    const float* __restrict__ Wq, const float* __restrict__ bq,
    const float* __restrict__ Wk, const float* __restrict__ bk,
    const float* __restrict__ Wv, const float* __restrict__ bv,
    const float* __restrict__ Wo, const float* __restrict__ bo,
    const float* __restrict__ Wff1, const float* __restrict__ Wff2,
    const float* __restrict__ gnorm, const float* __restrict__ bnorm,
    const float* __restrict__ Wdy, const float* __restrict__ bdy,
    const float* __restrict__ channels)
{
    // packed / aligned weight tiles (all pair-packed arrays 8B aligned)
    __shared__ __align__(16) float2 sWe2[294];   // [(ci*3+tap)*7 + op]
    __shared__ __align__(16) float  sbe[14];
    __shared__ __align__(16) float  sWq[112], sWk[112], sWv[112];   // [d*8+h]
    __shared__ __align__(16) float  sbq[8], sbk[8], sbv[8];
    __shared__ __align__(16) float  sWo[112];    // [h*14+d]
    __shared__ __align__(16) float  sbo[14];
    __shared__ __align__(16) float2 sF1t[350];   // [dp*50+f]
    __shared__ __align__(16) float  sF2[700];    // [f*14+d]
    __shared__ __align__(16) float  sg[14], sb[14];
    __shared__ __align__(16) float  sWdy[900], sbdy[30];
    __shared__ __align__(16) float  sAdj[196];   // [i*14+j]
    __shared__ __align__(16) float  scr[8][512]; // per-warp scratch

    const int tid = threadIdx.x;
    for (int i = tid; i < 294; i += 256) {
        int ct = i / 7, op = i - ct * 7;
        sWe2[i] = make_float2(W_emb[(2*op)*42 + ct], W_emb[(2*op+1)*42 + ct]);
    }
    for (int i = tid; i < 112; i += 256) { sWq[i]=Wq[i]; sWk[i]=Wk[i]; sWv[i]=Wv[i]; sWo[i]=Wo[i]; }
    for (int i = tid; i < 350; i += 256) {
        int dp = i / 50, f = i - dp * 50;
        sF1t[i] = make_float2(Wff1[(2*dp)*50 + f], Wff1[(2*dp+1)*50 + f]);
    }
    for (int i = tid; i < 700; i += 256) sF2[i] = Wff2[i];
    for (int i = tid; i < 900; i += 256) sWdy[i] = Wdy[i];
    if (tid < 30) sbdy[tid] = bdy[tid];
    if (tid < 14) { sbe[tid]=b_emb[tid]; sbo[tid]=bo[tid]; sg[tid]=gnorm[tid]; sb[tid]=bnorm[tid]; }
    if (tid < 8)  { sbq[tid]=bq[tid]; sbk[tid]=bk[tid]; sbv[tid]=bv[tid]; }
    if (tid < 14) {
        const float* row = channels + tid * 14;
        float mx = -1e30f;
        #pragma unroll
        for (int j = 0; j < 14; j++) mx = fmaxf(mx, row[j]);
        float s = 0.f;
        #pragma unroll
        for (int j = 0; j < 14; j++) s += expf(row[j] - mx);
        float inv = 1.f / s;
        #pragma unroll
        for (int j = 0; j < 14; j++) sAdj[tid * 14 + j] = expf(row[j] - mx) * inv;
    }
    __syncthreads();

    const int w    = tid >> 5;
    const int lane = tid & 31;
    const int t    = (lane < 30) ? lane : 0;
    const bool act = (lane < 30);
    const int smp  = blockIdx.x * 8 + w;

    // ---- coalesced stage of x ----
    {
        const float4* xp = reinterpret_cast<const float4*>(x + (size_t)smp * 420);
        float4* sp = reinterpret_cast<float4*>(scr[w]);
        #pragma unroll
        for (int i = lane; i < 105; i += 32) sp[i] = xp[i];
    }
    __syncwarp();
    float xr[14];
    #pragma unroll
    for (int d = 0; d < 14; d++) xr[d] = scr[w][t*14 + d];
    __syncwarp();

    // ---- Conv1d embed (kernel 3, zero pad): packed over output-channel pairs ----
    u64 xe2[7];
    {
        const u64* sbe2 = reinterpret_cast<const u64*>(sbe);
        #pragma unroll
        for (int op = 0; op < 7; op++) xe2[op] = sbe2[op];
        const u64* we = reinterpret_cast<const u64*>(sWe2);
        #pragma unroll
        for (int ci = 0; ci < 14; ci++) {
            float up = __shfl_up_sync(FULL, xr[ci], 1);
            float dn = __shfl_down_sync(FULL, xr[ci], 1);
            float xm  = (lane > 0)  ? up : 0.f;
            float xp2 = (lane < 29) ? dn : 0.f;
            float tap[3] = { xm, xr[ci], xp2 };
            #pragma unroll
            for (int tp = 0; tp < 3; tp++) {
                u64 xv2 = dup2(tap[tp]);
                const u64* wr = &we[(ci*3 + tp) * 7];
                #pragma unroll
                for (int op = 0; op < 7; op++) xe2[op] = fma2u(xv2, wr[op], xe2[op]);
            }
        }
    }
    // scalar copies of xe (needed for QKV broadcast operand)
    float xes[14];
    #pragma unroll
    for (int dp = 0; dp < 7; dp++) unpack2(xe2[dp], xes[2*dp], xes[2*dp+1]);

    // ---- QKV (packed over head pairs; Wq rows h-contiguous) ----
    u64 q2[4], k2[4], v2[4];
    {
        const u64* bq2 = reinterpret_cast<const u64*>(sbq);
        const u64* bk2 = reinterpret_cast<const u64*>(sbk);
        const u64* bv2 = reinterpret_cast<const u64*>(sbv);
        #pragma unroll
        for (int hp = 0; hp < 4; hp++) { q2[hp]=bq2[hp]; k2[hp]=bk2[hp]; v2[hp]=bv2[hp]; }
        const u64* wq2 = reinterpret_cast<const u64*>(sWq);
        const u64* wk2 = reinterpret_cast<const u64*>(sWk);
        const u64* wv2 = reinterpret_cast<const u64*>(sWv);
        #pragma unroll
        for (int d = 0; d < 14; d++) {
            u64 xv2 = dup2(xes[d]);
            #pragma unroll
            for (int hp = 0; hp < 4; hp++) {
                q2[hp] = fma2u(xv2, wq2[d*4+hp], q2[hp]);
                k2[hp] = fma2u(xv2, wk2[d*4+hp], k2[hp]);
                v2[hp] = fma2u(xv2, wv2[d*4+hp], v2[hp]);
            }
        }
    }
    float v[8];
    #pragma unroll
    for (int hp = 0; hp < 4; hp++) unpack2(v2[hp], v[2*hp], v[2*hp+1]);

    // stage q,k packed: qs2[hp*32+t] | ks2[hp*32+t]
    u64* qs2 = reinterpret_cast<u64*>(&scr[w][0]);
    u64* ks2 = reinterpret_cast<u64*>(&scr[w][256]);
    if (act) {
        #pragma unroll
        for (int hp = 0; hp < 4; hp++) { qs2[hp*32 + t] = q2[hp]; ks2[hp*32 + t] = k2[hp]; }
    }
    __syncwarp();

    // ---- circular correlation corr[tau] = sum_{t,h} q[t][h]*k[(t-tau)%30][h] ----
    float mv;
    {
        u64 acc2[4] = {};
        #pragma unroll
        for (int tq = 0; tq < 30; tq++) {
            int src = tq - t; if (src < 0) src += 30;
            #pragma unroll
            for (int hp = 0; hp < 4; hp++)
                acc2[hp] = fma2u(qs2[hp*32 + tq], ks2[hp*32 + src], acc2[hp]);
        }
        u64 s2 = add2u(add2u(acc2[0], acc2[1]), add2u(acc2[2], acc2[3]));
        float sx, sy; unpack2(s2, sx, sy);
        mv = act ? (sx + sy) * 0.125f : -1e30f;
    }

    // ---- warp-parallel top-3 with first-index tie-break ----
    float wv0, wv1, wv2; int dl0, dl1, dl2;
    {
        float mrun = mv;
        #pragma unroll
        for (int p = 0; p < 3; p++) {
            float bv = mrun; int bi = lane;
            #pragma unroll
            for (int off = 16; off; off >>= 1) {
                float vo = __shfl_xor_sync(FULL, bv, off);
                int   io = __shfl_xor_sync(FULL, bi, off);
                if (vo > bv || (vo == bv && io < bi)) { bv = vo; bi = io; }
            }
            if (p == 0) { wv0 = bv; dl0 = bi; }
            else if (p == 1) { wv1 = bv; dl1 = bi; }
            else { wv2 = bv; dl2 = bi; }
            if (lane == bi) mrun = -1e30f;
        }
    }
    float e1 = expf(wv1 - wv0);
    float e2 = expf(wv2 - wv0);
    float inv = 1.f / (1.f + e1 + e2);
    float w0 = inv, w1 = e1 * inv, w2 = e2 * inv;

    // ---- delay aggregation via shuffles ----
    float agg[8];
    {
        int s0 = t + dl0; if (s0 >= 30) s0 -= 30;
        int s1 = t + dl1; if (s1 >= 30) s1 -= 30;
        int s2 = t + dl2; if (s2 >= 30) s2 -= 30;
        #pragma unroll
        for (int h = 0; h < 8; h++) {
            float a = w0 * __shfl_sync(FULL, v[h], s0);
            a      += w1 * __shfl_sync(FULL, v[h], s1);
            a      += w2 * __shfl_sync(FULL, v[h], s2);
            agg[h] = a;
        }
    }

    // ---- x1 = xe + agg @ Wo + bo  (packed; Wo d-contiguous) ----
    u64 x1u[7];
    {
        const u64* sbo2 = reinterpret_cast<const u64*>(sbo);
        #pragma unroll
        for (int dp = 0; dp < 7; dp++) x1u[dp] = add2u(xe2[dp], sbo2[dp]);
        #pragma unroll
        for (int h = 0; h < 8; h++) {
            u64 a2 = dup2(agg[h]);
            const u64* wo2 = reinterpret_cast<const u64*>(&sWo[h*14]);
            #pragma unroll
            for (int dp = 0; dp < 7; dp++) x1u[dp] = fma2u(a2, wo2[dp], x1u[dp]);
        }
    }

    // ---- series_decomp 1 ----
    const float fc0  = (t < 12) ? (float)(12 - t) : 0.f;
    const float fc29 = (t > 17) ? (float)(t - 17) : 0.f;
    const int hi   = (t + 12 > 29) ? 29 : t + 12;
    const int lom1 = t - 13;
    const int loix = (lom1 < 0) ? 0 : lom1;
    u64 xdu[7];
    #pragma unroll
    for (int dp = 0; dp < 7; dp++) {
        float vx, vy; unpack2(x1u[dp], vx, vy);
        float dx = decomp25(vx, lane, hi, loix, lom1, fc0, fc29);
        float dy = decomp25(vy, lane, hi, loix, lom1, fc0, fc29);
        xdu[dp] = pack2(dx, dy);
    }

    // ---- FFN: x2 = xd + gelu_exact(xd @ F1) @ F2 ----
    u64 x2u[7];
    {
        u64 y2[7] = {};
        const u64* f1 = reinterpret_cast<const u64*>(sF1t);
        #pragma unroll 5
        for (int f = 0; f < 50; f++) {
            u64 h2 = 0;
            #pragma unroll
            for (int dp = 0; dp < 7; dp++) h2 = fma2u(xdu[dp], f1[dp*50 + f], h2);
            float hx, hy; unpack2(h2, hx, hy);
            float hs = hx + hy;
            float g = 0.5f * hs * (1.f + erff(hs * 0.70710678118654752f));
            u64 g2 = dup2(g);
            const u64* f2r = reinterpret_cast<const u64*>(&sF2[f*14]);
            #pragma unroll
            for (int dp = 0; dp < 7; dp++) y2[dp] = fma2u(g2, f2r[dp], y2[dp]);
        }
        #pragma unroll
        for (int dp = 0; dp < 7; dp++) x2u[dp] = add2u(xdu[dp], y2[dp]);
    }

    // ---- series_decomp 2 + layernorm (scalar lanes) ----
    float x3x[7], x3y[7];
    #pragma unroll
    for (int dp = 0; dp < 7; dp++) {
        float vx, vy; unpack2(x2u[dp], vx, vy);
        x3x[dp] = decomp25(vx, lane, hi, loix, lom1, fc0, fc29);
        x3y[dp] = decomp25(vy, lane, hi, loix, lom1, fc0, fc29);
    }
    {
        float m = 0.f;
        #pragma unroll
        for (int dp = 0; dp < 7; dp++) m += x3x[dp] + x3y[dp];
        m *= (1.f / 14.f);
        float var = 0.f;
        #pragma unroll
        for (int dp = 0; dp < 7; dp++) {
            float dx = x3x[dp] - m, dy = x3y[dp] - m;
            var += dx * dx + dy * dy;
        }
        var *= (1.f / 14.f);
        float invs = rsqrtf(var + 1e-5f);
        #pragma unroll
        for (int dp = 0; dp < 7; dp++) {
            x3x[dp] = (x3x[dp] - m) * invs * sg[2*dp]   + sb[2*dp];
            x3y[dp] = (x3y[dp] - m) * invs * sg[2*dp+1] + sb[2*dp+1];
        }
    }

    // ---- DyConv: stage x3 pairs, accumulate over m (lane = l) ----
    __syncwarp();
    u64* x3s2 = reinterpret_cast<u64*>(&scr[w][0]);  // [m*7+dp]
    if (act) {
        #pragma unroll
        for (int dp = 0; dp < 7; dp++) x3s2[t*7 + dp] = pack2(x3x[dp], x3y[dp]);
    }
    __syncwarp();
    u64 accd2[7];
    {
        u64 bias2 = dup2(sbdy[t]);
        #pragma unroll
        for (int dp = 0; dp < 7; dp++) accd2[dp] = bias2;
        #pragma unroll
        for (int m = 0; m < 30; m++) {
            u64 wm2 = dup2(sWdy[m*30 + t]);
            #pragma unroll
            for (int dp = 0; dp < 7; dp++)
                accd2[dp] = fma2u(x3s2[m*7 + dp], wm2, accd2[dp]);
        }
    }

    // ---- dy = relu(adj @ h2) -> g_f ----
    {
        float* fo = g_f + (size_t)smp * 420;
        #pragma unroll
        for (int i = 0; i < 14; i++) {
            const u64* ar = reinterpret_cast<const u64*>(&sAdj[i*14]);
            u64 a2 = 0;
            #pragma unroll
            for (int jp = 0; jp < 7; jp++) a2 = fma2u(ar[jp], accd2[jp], a2);
            float ax, ay; unpack2(a2, ax, ay);
            if (act) fo[i*30 + t] = fmaxf(ax + ay, 0.f);
        }
    }
}

// ============================================================================
// Kernel B (tensor): hh = relu(f @ W1 + b1)  M=65536, K=420, N=256
// ============================================================================
__global__ __launch_bounds__(256) void kB(const float* __restrict__ W1,
                                          const float* __restrict__ b1)
{
    __shared__ __align__(16) float As[128][36];
    __shared__ __align__(16) float Bs[64][36];
    const int tid = threadIdx.x;
    const int lane = tid & 31, wid = tid >> 5;
    const int wm = wid >> 1, wn = wid & 1;
    const size_t mbase = (size_t)blockIdx.x * 128;
    const int nbase = blockIdx.y * 64;
    float c[2][4][4] = {};

    for (int k0 = 0; k0 < 448; k0 += 32) {
        {
            int m = tid >> 1;
            const float4* gr = reinterpret_cast<const float4*>(g_f + (mbase + m) * 420);
            #pragma unroll
            for (int i = 0; i < 4; i++) {
                int qf = (tid & 1) * 4 + i;
                int kq = (k0 >> 2) + qf;
                float4 vv = (kq < 105) ? gr[kq] : make_float4(0.f,0.f,0.f,0.f);
                *reinterpret_cast<float4*>(&As[m][qf*4]) = vv;
            }
        }
        {
            int kl = tid >> 3;
            int gk = k0 + kl;
            #pragma unroll
            for (int half = 0; half < 2; half++) {
                int n4 = ((tid & 7) + 8*half) * 4;
                float4 vv = make_float4(0.f,0.f,0.f,0.f);
                if (gk < 420)
                    vv = *reinterpret_cast<const float4*>(W1 + (size_t)gk*256 + nbase + n4);
                Bs[n4+0][kl] = vv.x; Bs[n4+1][kl] = vv.y;
                Bs[n4+2][kl] = vv.z; Bs[n4+3][kl] = vv.w;
            }
        }
        __syncthreads();
        #pragma unroll
        for (int ks = 0; ks < 4; ks++) {
            int kk = ks * 8;
            unsigned ah[2][4], al[2][4], bh[4][2], bl[4][2];
            #pragma unroll
            for (int mt = 0; mt < 2; mt++) {
                int r = wm*32 + mt*16 + (lane>>2);
                split_tf32(As[r  ][kk + (lane&3)    ], ah[mt][0], al[mt][0]);
                split_tf32(As[r+8][kk + (lane&3)    ], ah[mt][1], al[mt][1]);
                split_tf32(As[r  ][kk + (lane&3) + 4], ah[mt][2], al[mt][2]);
                split_tf32(As[r+8][kk + (lane&3) + 4], ah[mt][3], al[mt][3]);
            }
            #pragma unroll
            for (int nt = 0; nt < 4; nt++) {
                int nn = wn*32 + nt*8 + (lane>>2);
                split_tf32(Bs[nn][kk + (lane&3)    ], bh[nt][0], bl[nt][0]);
                split_tf32(Bs[nn][kk + (lane&3) + 4], bh[nt][1], bl[nt][1]);
            }
            #pragma unroll
            for (int mt = 0; mt < 2; mt++)
                #pragma unroll
                for (int nt = 0; nt < 4; nt++) {
                    mma_tf32(c[mt][nt], ah[mt], bh[nt]);
                    mma_tf32(c[mt][nt], ah[mt], bl[nt]);
                    mma_tf32(c[mt][nt], al[mt], bh[nt]);
                }
        }
        __syncthreads();
    }
    #pragma unroll
    for (int mt = 0; mt < 2; mt++) {
        int r0 = wm*32 + mt*16 + (lane>>2);
        #pragma unroll
        for (int nt = 0; nt < 4; nt++) {
            int cl = nbase + wn*32 + nt*8 + 2*(lane&3);
            float b0 = b1[cl], b1v = b1[cl+1];
            float2 lo = make_float2(fmaxf(c[mt][nt][0] + b0, 0.f), fmaxf(c[mt][nt][1] + b1v, 0.f));
            float2 hi = make_float2(fmaxf(c[mt][nt][2] + b0, 0.f), fmaxf(c[mt][nt][3] + b1v, 0.f));
            *reinterpret_cast<float2*>(g_hh + (mbase + r0    ) * 256 + cl) = lo;
            *reinterpret_cast<float2*>(g_hh + (mbase + r0 + 8) * 256 + cl) = hi;
        }
    }
}

// ============================================================================
// Kernel C (tensor): hr = [hh|f] @ [W2;Wres] + b2 + bres  M=65536, K=676, N=64
// ============================================================================
__global__ __launch_bounds__(256) void kC(const float* __restrict__ W2,
                                          const float* __restrict__ b2,
                                          const float* __restrict__ Wres,
                                          const float* __restrict__ bres)
{
    __shared__ __align__(16) float As[128][36];
    __shared__ __align__(16) float Bs[64][36];
    const int tid = threadIdx.x;
    const int lane = tid & 31, wid = tid >> 5;
    const int wm = wid >> 1, wn = wid & 1;
    const size_t mbase = (size_t)blockIdx.x * 128;
    float c[2][4][4] = {};

    for (int k0 = 0; k0 < 704; k0 += 32) {
        {
            int m = tid >> 1;
            const float* hrow = g_hh + (mbase + m) * 256;
            const float* frow = g_f  + (mbase + m) * 420;
            #pragma unroll
            for (int i = 0; i < 4; i++) {
                int qf = (tid & 1) * 4 + i;
                int gk = k0 + qf*4;
                float4 vv = make_float4(0.f,0.f,0.f,0.f);
                if (gk < 256) vv = *reinterpret_cast<const float4*>(hrow + gk);
                else { int kf = gk - 256; if (kf < 420) vv = *reinterpret_cast<const float4*>(frow + kf); }
                *reinterpret_cast<float4*>(&As[m][qf*4]) = vv;
            }
        }
        {
            int kl = tid >> 3;
            int gk = k0 + kl;
            #pragma unroll
            for (int half = 0; half < 2; half++) {
                int n4 = ((tid & 7) + 8*half) * 4;
                float4 vv = make_float4(0.f,0.f,0.f,0.f);
                if (gk < 256) vv = *reinterpret_cast<const float4*>(W2 + (size_t)gk*64 + n4);
                else { int kf = gk - 256; if (kf < 420) vv = *reinterpret_cast<const float4*>(Wres + (size_t)kf*64 + n4); }
                Bs[n4+0][kl] = vv.x; Bs[n4+1][kl] = vv.y;
                Bs[n4+2][kl] = vv.z; Bs[n4+3][kl] = vv.w;
            }
        }
        __syncthreads();
        #pragma unroll
        for (int ks = 0; ks < 4; ks++) {
            int kk = ks * 8;
            unsigned ah[2][4], al[2][4], bh[4][2], bl[4][2];
            #pragma unroll
            for (int mt = 0; mt < 2; mt++) {
                int r = wm*32 + mt*16 + (lane>>2);
                split_tf32(As[r  ][kk + (lane&3)    ], ah[mt][0], al[mt][0]);
                split_tf32(As[r+8][kk + (lane&3)    ], ah[mt][1], al[mt][1]);
                split_tf32(As[r  ][kk + (lane&3) + 4], ah[mt][2], al[mt][2]);
                split_tf32(As[r+8][kk + (lane&3) + 4], ah[mt][3], al[mt][3]);
            }
            #pragma unroll
            for (int nt = 0; nt < 4; nt++) {
                int nn = wn*32 + nt*8 + (lane>>2);
                split_tf32(Bs[nn][kk + (lane&3)    ], bh[nt][0], bl[nt][0]);
                split_tf32(Bs[nn][kk + (lane&3) + 4], bh[nt][1], bl[nt][1]);
            }
            #pragma unroll
            for (int mt = 0; mt < 2; mt++)
                #pragma unroll
                for (int nt = 0; nt < 4; nt++) {
                    mma_tf32(c[mt][nt], ah[mt], bh[nt]);
                    mma_tf32(c[mt][nt], ah[mt], bl[nt]);
                    mma_tf32(c[mt][nt], al[mt], bh[nt]);
                }
        }
        __syncthreads();
    }
    #pragma unroll
    for (int mt = 0; mt < 2; mt++) {
        int r0 = wm*32 + mt*16 + (lane>>2);
        #pragma unroll
        for (int nt = 0; nt < 4; nt++) {
            int cl = wn*32 + nt*8 + 2*(lane&3);
            float b0 = b2[cl] + bres[cl], b1v = b2[cl+1] + bres[cl+1];
            float2 lo = make_float2(c[mt][nt][0] + b0, c[mt][nt][1] + b1v);
            float2 hi = make_float2(c[mt][nt][2] + b0, c[mt][nt][3] + b1v);
            *reinterpret_cast<float2*>(g_hr + (mbase + r0    ) * 64 + cl) = lo;
            *reinterpret_cast<float2*>(g_hr + (mbase + r0 + 8) * 64 + cl) = hi;
        }
    }
}

// ============================================================================
// Kernel D: out = LN64(hr) @ W3 + b3   (one warp per sample)
// ============================================================================
__global__ __launch_bounds__(256) void kD(const float* __restrict__ g_ln,
                                          const float* __restrict__ b_ln,
                                          const float* __restrict__ W3,
                                          const float* __restrict__ b3,
                                          float* __restrict__ out)
{
    int w = threadIdx.x >> 5, lane = threadIdx.x & 31;
    size_t s = (size_t)blockIdx.x * 8 + w;
    const float* r = g_hr + s * 64;
    float v0 = r[lane], v1 = r[lane + 32];
    float sum = v0 + v1, sq = v0 * v0 + v1 * v1;
    #pragma unroll
    for (int o = 16; o; o >>= 1) {
        sum += __shfl_xor_sync(FULL, sum, o);
        sq  += __shfl_xor_sync(FULL, sq,  o);
    }
    float m = sum * (1.f / 64.f);
    float var = sq * (1.f / 64.f) - m * m;
    float inv = rsqrtf(var + 1e-5f);
    float y0 = (v0 - m) * inv * g_ln[lane]      + b_ln[lane];
    float y1 = (v1 - m) * inv * g_ln[lane + 32] + b_ln[lane + 32];
    float d = y0 * W3[lane] + y1 * W3[lane + 32];
    #pragma unroll
    for (int o = 16; o; o >>= 1) d += __shfl_xor_sync(FULL, d, o);
    if (lane == 0) out[s] = d + b3[0];
}

// ============================================================================
extern "C" void kernel_launch(void* const* d_in, const int* in_sizes, int n_in,
                              void* d_out, int out_size)
{
    (void)in_sizes; (void)n_in; (void)out_size;
    const float* x = (const float*)d_in[0];

    kA<<<BATCH / 8, 256>>>(x,
        (const float*)d_in[1],  (const float*)d_in[2],
        (const float*)d_in[3],  (const float*)d_in[4],
        (const float*)d_in[5],  (const float*)d_in[6],
        (const float*)d_in[7],  (const float*)d_in[8],
        (const float*)d_in[9],  (const float*)d_in[10],
        (const float*)d_in[11], (const float*)d_in[12],
        (const float*)d_in[13], (const float*)d_in[14],
        (const float*)d_in[15], (const float*)d_in[16],
        (const float*)d_in[17]);

    kB<<<dim3(BATCH / 128, 4), 256>>>((const float*)d_in[18], (const float*)d_in[19]);

    kC<<<BATCH / 128, 256>>>((const float*)d_in[20], (const float*)d_in[21],
                             (const float*)d_in[22], (const float*)d_in[23]);

    kD<<<BATCH / 8, 256>>>((const float*)d_in[24], (const float*)d_in[25],
                           (const float*)d_in[26], (const float*)d_in[27],
                           (float*)d_out);
}